// round 7
// baseline (speedup 1.0000x reference)
#include <cuda_runtime.h>

#define NN 50000
#define EE 800000
#define HCH 64
#define ECH 32
#define NHD 4
#define PH 16

// Scratch (device globals; no allocation allowed). 16B-aligned for float4/red.v4.
__device__ __align__(16) float g_K [NN * HCH];   // per-node keys   (n, h, 16)
__device__ __align__(16) float g_V [NN * HCH];   // per-node values (n, h, 16)
__device__ __align__(16) float g_Qt[NN * HCH];   // q~ = wkl^T q    (n, h, 16)
__device__ __align__(16) float g_Qb[NN * NHD];   // q . wkl_b       (n, h)
__device__ __align__(16) float g_U [NN * HCH];   // atomic accum:   sum_e e * W_v * v_col
__device__ __align__(16) float g_D [NN * NHD];   // atomic accum:   sum_e e
__device__ int g_idx64;                          // 1 if edge_index is int64

__device__ __forceinline__ float ssp(float v) {
    // softplus(v) - ln 2, numerically stable
    return fmaxf(v, 0.f) + log1pf(__expf(-fabsf(v))) - 0.69314718055994531f;
}

__device__ __forceinline__ void ld16(const float* __restrict__ p, float* r) {
#pragma unroll
    for (int i = 0; i < 4; i++) {
        float4 v = reinterpret_cast<const float4*>(p)[i];
        r[4*i+0] = v.x; r[4*i+1] = v.y; r[4*i+2] = v.z; r[4*i+3] = v.w;
    }
}

__device__ __forceinline__ void st16(float* p, const float* r) {
#pragma unroll
    for (int i = 0; i < 4; i++) {
        reinterpret_cast<float4*>(p)[i] =
            make_float4(r[4*i+0], r[4*i+1], r[4*i+2], r[4*i+3]);
    }
}

__device__ __forceinline__ void red_add4(float* p, float a, float b, float c, float d) {
    asm volatile("red.global.add.v4.f32 [%0], {%1,%2,%3,%4};"
                 :: "l"(__cvta_generic_to_global(p)),
                    "f"(a), "f"(b), "f"(c), "f"(d) : "memory");
}

// ---------------------------------------------------------------------------
// Kernel 0: detect edge_index width. PARALLEL: 256 threads sample the high
// 32-bit words; int64 node ids < 50000 have all-zero high words.
// ---------------------------------------------------------------------------
__global__ void k_detect(const int* __restrict__ ei_w) {
    int bad = __syncthreads_or(ei_w[2 * threadIdx.x + 1] != 0);
    if (threadIdx.x == 0) g_idx64 = bad ? 0 : 1;
}

// ---------------------------------------------------------------------------
// Kernel 1: per-(node, head) precompute K, V, Q~ = wkl^T q, qb = q.wkl_b.
// Also zeroes the atomic accumulators.
// ---------------------------------------------------------------------------
__global__ __launch_bounds__(256)
void k_nodes(const float* __restrict__ x,
             const float* __restrict__ kw, const float* __restrict__ qw,
             const float* __restrict__ vw,
             const float* __restrict__ wklw, const float* __restrict__ wklb) {
    __shared__ float s_k[1024], s_q[1024], s_v[1024], s_l[256], s_lb[16];
    for (int i = threadIdx.x; i < 1024; i += 256) {
        s_k[i] = kw[i]; s_q[i] = qw[i]; s_v[i] = vw[i];
    }
    if (threadIdx.x < 256) s_l[threadIdx.x] = wklw[threadIdx.x];
    if (threadIdx.x < 16)  s_lb[threadIdx.x] = wklb[threadIdx.x];
    __syncthreads();

    int t = blockIdx.x * 256 + threadIdx.x;
    if (t >= NN * NHD) return;
    int n = t >> 2, h = t & 3;

    float xv[PH];
    ld16(x + (size_t)n * HCH + h * PH, xv);

    const float4* wkh = (const float4*)(s_k + h * 256);
    const float4* wqh = (const float4*)(s_q + h * 256);
    const float4* wvh = (const float4*)(s_v + h * 256);

    float kk[PH], vv[PH], qq[PH];
#pragma unroll
    for (int o = 0; o < PH; o++) {
        float a = 0.f, b = 0.f, c = 0.f;
#pragma unroll
        for (int q = 0; q < 4; q++) {
            float4 wk = wkh[o * 4 + q];
            float4 wq = wqh[o * 4 + q];
            float4 wv = wvh[o * 4 + q];
            a += xv[4*q]*wk.x + xv[4*q+1]*wk.y + xv[4*q+2]*wk.z + xv[4*q+3]*wk.w;
            b += xv[4*q]*wq.x + xv[4*q+1]*wq.y + xv[4*q+2]*wq.z + xv[4*q+3]*wq.w;
            c += xv[4*q]*wv.x + xv[4*q+1]*wv.y + xv[4*q+2]*wv.z + xv[4*q+3]*wv.w;
        }
        kk[o] = a; qq[o] = b; vv[o] = c;
    }

    float qt[PH];
#pragma unroll
    for (int i = 0; i < PH; i++) {
        float a = 0.f;
#pragma unroll
        for (int o = 0; o < PH; o++) a += qq[o] * s_l[o * PH + i];
        qt[i] = a;
    }
    float qb = 0.f;
#pragma unroll
    for (int o = 0; o < PH; o++) qb += qq[o] * s_lb[o];

    st16(g_K  + (size_t)t * PH, kk);
    st16(g_V  + (size_t)t * PH, vv);
    st16(g_Qt + (size_t)t * PH, qt);
    g_Qb[t] = qb;

    // zero accumulators
    float4 z = make_float4(0.f, 0.f, 0.f, 0.f);
#pragma unroll
    for (int i = 0; i < 4; i++)
        reinterpret_cast<float4*>(g_U + (size_t)t * PH)[i] = z;
    g_D[t] = 0.f;
}

// ---------------------------------------------------------------------------
// Kernel 2: single edge pass. One thread per edge; 256 edges per block.
//   - edge_attr staged coalesced through shared (padded rows, float4).
//   - weight broadcasts vectorized as float4 (4 FMA per LDS.128).
// ---------------------------------------------------------------------------
__global__ __launch_bounds__(256)
void k_edges(const int* __restrict__ ei, const float* __restrict__ ea,
             const float* __restrict__ wk1, const float* __restrict__ bk1,
             const float* __restrict__ wk2, const float* __restrict__ bk2,
             const float* __restrict__ wv1, const float* __restrict__ bv1,
             const float* __restrict__ wv2, const float* __restrict__ bv2) {
    __shared__ float4 s_ea[256 * 9];            // row stride 9 float4 (36 floats)
    __shared__ float s_wk1[512], s_wv1[512], s_wk2[256], s_wv2[256];
    __shared__ float s_bk1[16], s_bk2[16], s_bv1[16], s_bv2[16];
    int tid = threadIdx.x;

    for (int i = tid; i < 512; i += 256) { s_wk1[i] = wk1[i]; s_wv1[i] = wv1[i]; }
    { s_wk2[tid] = wk2[tid]; s_wv2[tid] = wv2[tid]; }
    if (tid < 16) {
        s_bk1[tid] = bk1[tid]; s_bk2[tid] = bk2[tid];
        s_bv1[tid] = bv1[tid]; s_bv2[tid] = bv2[tid];
    }

    // stage edge_attr for this block's 256 edges (fully coalesced)
    long long e0 = (long long)blockIdx.x * 256;
    const float4* ea4 = reinterpret_cast<const float4*>(ea + (size_t)e0 * ECH);
#pragma unroll
    for (int k = 0; k < 8; k++) {
        int f = tid + k * 256;                  // float4 index in [0, 2048)
        float4 v = ea4[f];
        s_ea[(f >> 3) * 9 + (f & 7)] = v;
    }
    __syncthreads();

    int e = (int)e0 + tid;
    int row, col;
    if (g_idx64) {
        const long long* p = (const long long*)ei;
        row = (int)p[e];
        col = (int)p[(size_t)EE + e];
    } else {
        row = ei[e];
        col = ei[EE + e];
    }

    float eav[ECH];
#pragma unroll
    for (int q = 0; q < 8; q++) {
        float4 v = s_ea[tid * 9 + q];
        eav[4*q+0] = v.x; eav[4*q+1] = v.y; eav[4*q+2] = v.z; eav[4*q+3] = v.w;
    }

    const float4* wk1v = (const float4*)s_wk1;
    const float4* wv1v = (const float4*)s_wv1;
    const float4* wk2v = (const float4*)s_wk2;
    const float4* wv2v = (const float4*)s_wv2;

    // layer 1 (both nets share the input); float4 broadcast weight reads
    float tk[PH], tv[PH];
#pragma unroll
    for (int j = 0; j < PH; j++) {
        float a = s_bk1[j], b = s_bv1[j];
#pragma unroll
        for (int q = 0; q < 8; q++) {
            float4 wk = wk1v[j * 8 + q];
            float4 wv = wv1v[j * 8 + q];
            a += eav[4*q]*wk.x + eav[4*q+1]*wk.y + eav[4*q+2]*wk.z + eav[4*q+3]*wk.w;
            b += eav[4*q]*wv.x + eav[4*q+1]*wv.y + eav[4*q+2]*wv.z + eav[4*q+3]*wv.w;
        }
        tk[j] = ssp(a); tv[j] = ssp(b);
    }
    // layer 2
    float wkv[PH], wvv[PH];
#pragma unroll
    for (int o = 0; o < PH; o++) {
        float a = s_bk2[o], b = s_bv2[o];
#pragma unroll
        for (int q = 0; q < 4; q++) {
            float4 wk = wk2v[o * 4 + q];
            float4 wv = wv2v[o * 4 + q];
            a += tk[4*q]*wk.x + tk[4*q+1]*wk.y + tk[4*q+2]*wk.z + tk[4*q+3]*wk.w;
            b += tv[4*q]*wv.x + tv[4*q+1]*wv.y + tv[4*q+2]*wv.z + tv[4*q+3]*wv.w;
        }
        wkv[o] = a; wvv[o] = b;
    }

    const float* Kc = g_K  + (size_t)col * HCH;
    const float* Vc = g_V  + (size_t)col * HCH;
    const float* Qt = g_Qt + (size_t)row * HCH;
    float*       Up = g_U  + (size_t)row * HCH;

    float4 qb4 = *reinterpret_cast<const float4*>(g_Qb + row * NHD);
    float qbr[4] = {qb4.x, qb4.y, qb4.z, qb4.w};

#pragma unroll
    for (int h = 0; h < NHD; h++) {
        float kr[PH], qr[PH];
        ld16(Kc + h * PH, kr);
        ld16(Qt + h * PH, qr);
        float s = qbr[h];
#pragma unroll
        for (int i = 0; i < PH; i++) s += (wkv[i] * kr[i]) * qr[i];
        float eh = __expf(s);
        atomicAdd(&g_D[row * NHD + h], eh);

        float vr[PH];
        ld16(Vc + h * PH, vr);
#pragma unroll
        for (int q = 0; q < 4; q++) {
            red_add4(Up + h * PH + 4 * q,
                     eh * wvv[4*q+0] * vr[4*q+0],
                     eh * wvv[4*q+1] * vr[4*q+1],
                     eh * wvv[4*q+2] * vr[4*q+2],
                     eh * wvv[4*q+3] * vr[4*q+3]);
        }
    }
}

// ---------------------------------------------------------------------------
// Kernel 3: per node (thread = node). Weights read as warp-uniform float4
// broadcasts from shared; x and U loaded straight to registers; t and y
// exchanged through a padded shared row; final store coalesced.
//   aggr = (wvl @ U)/D + wvl_b (if D>0)
//   y = out_w @ ssp(cen_w @ x + cen_b + aggr) + out_b
// ---------------------------------------------------------------------------
#define ONB 128
__global__ __launch_bounds__(ONB)
void k_out(const float* __restrict__ x,
           const float* __restrict__ wvlw, const float* __restrict__ wvlb,
           const float* __restrict__ cenw, const float* __restrict__ cenb,
           const float* __restrict__ outw, const float* __restrict__ outb,
           float* __restrict__ y) {
    __shared__ float s_cen[4096], s_out[4096], s_wvl[256];
    __shared__ float s_cb[64], s_ob[64], s_vb[16];
    __shared__ float s_t[ONB * 68];            // padded row (68 = 17 float4)

    int tid = threadIdx.x;
    for (int i = tid; i < 4096; i += ONB) { s_cen[i] = cenw[i]; s_out[i] = outw[i]; }
    for (int i = tid; i < 256; i += ONB) s_wvl[i] = wvlw[i];
    if (tid < 64) { s_cb[tid] = cenb[tid]; s_ob[tid] = outb[tid]; }
    if (tid < 16) s_vb[tid] = wvlb[tid];
    __syncthreads();

    int n = blockIdx.x * ONB + tid;
    bool valid = n < NN;
    int nc = valid ? n : (NN - 1);
    float* myrow = s_t + tid * 68;

    // phase 1: aggr (uses U + D), write to own shared row
    {
        const float4* u4 = (const float4*)(g_U + (size_t)nc * HCH);
        float uu[64];
#pragma unroll
        for (int q = 0; q < 16; q++) {
            float4 v = u4[q];
            uu[4*q] = v.x; uu[4*q+1] = v.y; uu[4*q+2] = v.z; uu[4*q+3] = v.w;
        }
        float4 dd = *(const float4*)(g_D + nc * NHD);
        float dar[4] = {dd.x, dd.y, dd.z, dd.w};
        const float4* wvl4 = (const float4*)s_wvl;
#pragma unroll
        for (int o = 0; o < 64; o++) {
            int h = o >> 4, oo = o & 15;
            float s2 = 0.f;
#pragma unroll
            for (int q = 0; q < 4; q++) {
                float4 w = wvl4[oo * 4 + q];
                s2 += uu[h*16+4*q]*w.x + uu[h*16+4*q+1]*w.y
                    + uu[h*16+4*q+2]*w.z + uu[h*16+4*q+3]*w.w;
            }
            float d = dar[h];
            myrow[o] = (d > 0.f) ? (s2 / d + s_vb[oo]) : 0.f;
        }
    }

    // phase 2: t = ssp(cen @ x + cb + aggr), in place on own row
    {
        const float4* x4 = (const float4*)(x + (size_t)nc * HCH);
        float xv[64];
#pragma unroll
        for (int q = 0; q < 16; q++) {
            float4 v = x4[q];
            xv[4*q] = v.x; xv[4*q+1] = v.y; xv[4*q+2] = v.z; xv[4*q+3] = v.w;
        }
        const float4* cen4 = (const float4*)s_cen;
#pragma unroll
        for (int o = 0; o < 64; o++) {
            float a = s_cb[o];
#pragma unroll
            for (int q = 0; q < 16; q++) {
                float4 w = cen4[o * 16 + q];
                a += xv[4*q]*w.x + xv[4*q+1]*w.y + xv[4*q+2]*w.z + xv[4*q+3]*w.w;
            }
            myrow[o] = ssp(a + myrow[o]);
        }
    }

    // phase 3: y = out @ t + ob, back into own row
    {
        float tv[64];
#pragma unroll
        for (int q = 0; q < 16; q++) {
            float4 v = *(const float4*)(myrow + 4 * q);
            tv[4*q] = v.x; tv[4*q+1] = v.y; tv[4*q+2] = v.z; tv[4*q+3] = v.w;
        }
        const float4* out4 = (const float4*)s_out;
#pragma unroll
        for (int o = 0; o < 64; o++) {
            float a = s_ob[o];
#pragma unroll
            for (int q = 0; q < 16; q++) {
                float4 w = out4[o * 16 + q];
                a += tv[4*q]*w.x + tv[4*q+1]*w.y + tv[4*q+2]*w.z + tv[4*q+3]*w.w;
            }
            myrow[o] = a;
        }
    }
    __syncthreads();

    // phase 4: coalesced store of the block's 128x64 tile
    {
        size_t base4 = (size_t)blockIdx.x * ONB * 16;   // float4 units
        float4* y4 = reinterpret_cast<float4*>(y);
#pragma unroll
        for (int k = 0; k < 16; k++) {
            int f = tid + k * ONB;                      // [0, 2048)
            int r = f >> 4, c = f & 15;
            if (blockIdx.x * ONB + r < NN)
                y4[base4 + f] = *(const float4*)(s_t + r * 68 + c * 4);
        }
    }
}

// ---------------------------------------------------------------------------
extern "C" void kernel_launch(void* const* d_in, const int* in_sizes, int n_in,
                              void* d_out, int out_size) {
    const float* x    = (const float*)d_in[0];
    const int*   ei   = (const int*)d_in[1];
    const float* ea   = (const float*)d_in[2];
    const float* kw   = (const float*)d_in[3];
    const float* qw   = (const float*)d_in[4];
    const float* vw   = (const float*)d_in[5];
    const float* wk1  = (const float*)d_in[6];
    const float* bk1  = (const float*)d_in[7];
    const float* wk2  = (const float*)d_in[8];
    const float* bk2  = (const float*)d_in[9];
    const float* wklw = (const float*)d_in[10];
    const float* wklb = (const float*)d_in[11];
    const float* wv1  = (const float*)d_in[12];
    const float* bv1  = (const float*)d_in[13];
    const float* wv2  = (const float*)d_in[14];
    const float* bv2  = (const float*)d_in[15];
    const float* wvlw = (const float*)d_in[16];
    const float* wvlb = (const float*)d_in[17];
    const float* cenw = (const float*)d_in[18];
    const float* cenb = (const float*)d_in[19];
    const float* outw = (const float*)d_in[20];
    const float* outb = (const float*)d_in[21];
    float* out = (float*)d_out;

    k_detect<<<1, 256>>>(ei);
    k_nodes<<<(NN * NHD + 255) / 256, 256>>>(x, kw, qw, vw, wklw, wklb);
    k_edges<<<EE / 256, 256>>>(ei, ea, wk1, bk1, wk2, bk2,
                               wv1, bv1, wv2, bv2);
    k_out<<<(NN + ONB - 1) / ONB, ONB>>>(x, wvlw, wvlb, cenw, cenb,
                                         outw, outb, out);
}

// round 8
// speedup vs baseline: 1.1501x; 1.1501x over previous
#include <cuda_runtime.h>

#define NN 50000
#define EE 800000
#define HCH 64
#define ECH 32
#define NHD 4
#define PH 16

typedef unsigned long long u64;

// Scratch (device globals; no allocation allowed). 16B-aligned for float4/red.v4.
__device__ __align__(16) float g_K [NN * HCH];   // per-node keys   (n, h, 16)
__device__ __align__(16) float g_V [NN * HCH];   // per-node values (n, h, 16)
__device__ __align__(16) float g_Qt[NN * HCH];   // q~ = wkl^T q    (n, h, 16)
__device__ __align__(16) float g_Qb[NN * NHD];   // q . wkl_b       (n, h)
__device__ __align__(16) float g_U [NN * HCH];   // atomic accum:   sum_e e * W_v * v_col
__device__ __align__(16) float g_D [NN * NHD];   // atomic accum:   sum_e e
__device__ int g_idx64;                          // 1 if edge_index is int64

__device__ __forceinline__ float ssp(float v) {
    return fmaxf(v, 0.f) + log1pf(__expf(-fabsf(v))) - 0.69314718055994531f;
}

// ---- packed f32x2 helpers (sm_103a) ----
__device__ __forceinline__ u64 pack2(float lo, float hi) {
    u64 d; asm("mov.b64 %0, {%1, %2};" : "=l"(d) : "f"(lo), "f"(hi)); return d;
}
__device__ __forceinline__ void unpack2(u64 a, float& lo, float& hi) {
    asm("mov.b64 {%0, %1}, %2;" : "=f"(lo), "=f"(hi) : "l"(a));
}
__device__ __forceinline__ u64 ffma2(u64 a, u64 b, u64 c) {
    u64 d; asm("fma.rn.f32x2 %0, %1, %2, %3;" : "=l"(d) : "l"(a), "l"(b), "l"(c)); return d;
}
__device__ __forceinline__ u64 fmul2(u64 a, u64 b) {
    u64 d; asm("mul.rn.f32x2 %0, %1, %2;" : "=l"(d) : "l"(a), "l"(b)); return d;
}

__device__ __forceinline__ void ld16(const float* __restrict__ p, float* r) {
#pragma unroll
    for (int i = 0; i < 4; i++) {
        float4 v = reinterpret_cast<const float4*>(p)[i];
        r[4*i+0] = v.x; r[4*i+1] = v.y; r[4*i+2] = v.z; r[4*i+3] = v.w;
    }
}
// load 16 floats as 8 packed f32x2
__device__ __forceinline__ void ld16p(const float* __restrict__ p, u64* r) {
#pragma unroll
    for (int i = 0; i < 4; i++) {
        float4 v = reinterpret_cast<const float4*>(p)[i];
        r[2*i]   = pack2(v.x, v.y);
        r[2*i+1] = pack2(v.z, v.w);
    }
}

__device__ __forceinline__ void st16(float* p, const float* r) {
#pragma unroll
    for (int i = 0; i < 4; i++) {
        reinterpret_cast<float4*>(p)[i] =
            make_float4(r[4*i+0], r[4*i+1], r[4*i+2], r[4*i+3]);
    }
}

__device__ __forceinline__ void red_add4(float* p, float a, float b, float c, float d) {
    asm volatile("red.global.add.v4.f32 [%0], {%1,%2,%3,%4};"
                 :: "l"(__cvta_generic_to_global(p)),
                    "f"(a), "f"(b), "f"(c), "f"(d) : "memory");
}

// ---------------------------------------------------------------------------
// Kernel 0: detect edge_index width (int64 node ids < 50000 -> high words 0).
// ---------------------------------------------------------------------------
__global__ void k_detect(const int* __restrict__ ei_w) {
    int bad = __syncthreads_or(ei_w[2 * threadIdx.x + 1] != 0);
    if (threadIdx.x == 0) g_idx64 = bad ? 0 : 1;
}

// ---------------------------------------------------------------------------
// Kernel 1: per-(node, head) precompute K, V, Q~ = wkl^T q, qb = q.wkl_b.
// Also zeroes the atomic accumulators.
// ---------------------------------------------------------------------------
__global__ __launch_bounds__(256)
void k_nodes(const float* __restrict__ x,
             const float* __restrict__ kw, const float* __restrict__ qw,
             const float* __restrict__ vw,
             const float* __restrict__ wklw, const float* __restrict__ wklb) {
    __shared__ __align__(16) float s_k[1024], s_q[1024], s_v[1024], s_l[256], s_lb[16];
    for (int i = threadIdx.x; i < 1024; i += 256) {
        s_k[i] = kw[i]; s_q[i] = qw[i]; s_v[i] = vw[i];
    }
    if (threadIdx.x < 256) s_l[threadIdx.x] = wklw[threadIdx.x];
    if (threadIdx.x < 16)  s_lb[threadIdx.x] = wklb[threadIdx.x];
    __syncthreads();

    int t = blockIdx.x * 256 + threadIdx.x;
    if (t >= NN * NHD) return;
    int n = t >> 2, h = t & 3;

    float xv[PH];
    ld16(x + (size_t)n * HCH + h * PH, xv);

    const float4* wkh = (const float4*)(s_k + h * 256);
    const float4* wqh = (const float4*)(s_q + h * 256);
    const float4* wvh = (const float4*)(s_v + h * 256);

    float kk[PH], vv[PH], qq[PH];
#pragma unroll
    for (int o = 0; o < PH; o++) {
        float a = 0.f, b = 0.f, c = 0.f;
#pragma unroll
        for (int q = 0; q < 4; q++) {
            float4 wk = wkh[o * 4 + q];
            float4 wq = wqh[o * 4 + q];
            float4 wv = wvh[o * 4 + q];
            a += xv[4*q]*wk.x + xv[4*q+1]*wk.y + xv[4*q+2]*wk.z + xv[4*q+3]*wk.w;
            b += xv[4*q]*wq.x + xv[4*q+1]*wq.y + xv[4*q+2]*wq.z + xv[4*q+3]*wq.w;
            c += xv[4*q]*wv.x + xv[4*q+1]*wv.y + xv[4*q+2]*wv.z + xv[4*q+3]*wv.w;
        }
        kk[o] = a; qq[o] = b; vv[o] = c;
    }

    float qt[PH];
#pragma unroll
    for (int i = 0; i < PH; i++) {
        float a = 0.f;
#pragma unroll
        for (int o = 0; o < PH; o++) a += qq[o] * s_l[o * PH + i];
        qt[i] = a;
    }
    float qb = 0.f;
#pragma unroll
    for (int o = 0; o < PH; o++) qb += qq[o] * s_lb[o];

    st16(g_K  + (size_t)t * PH, kk);
    st16(g_V  + (size_t)t * PH, vv);
    st16(g_Qt + (size_t)t * PH, qt);
    g_Qb[t] = qb;

    float4 z = make_float4(0.f, 0.f, 0.f, 0.f);
#pragma unroll
    for (int i = 0; i < 4; i++)
        reinterpret_cast<float4*>(g_U + (size_t)t * PH)[i] = z;
    g_D[t] = 0.f;
}

// ---------------------------------------------------------------------------
// Kernel 2: single edge pass, 128 threads = 128 edges per block.
// MLPs computed with packed fma.rn.f32x2 (input-pairing: two partial sums in
// the f32x2 lanes, horizontal add at the end) -> weights reinterpret in place.
// ---------------------------------------------------------------------------
#define ENB 128
__global__ __launch_bounds__(ENB)
void k_edges(const int* __restrict__ ei, const float* __restrict__ ea,
             const float* __restrict__ wk1, const float* __restrict__ bk1,
             const float* __restrict__ wk2, const float* __restrict__ bk2,
             const float* __restrict__ wv1, const float* __restrict__ bv1,
             const float* __restrict__ wv2, const float* __restrict__ bv2) {
    __shared__ __align__(16) float4 s_ea[ENB * 9];      // row stride 9 float4
    __shared__ __align__(16) float s_wk1[512], s_wv1[512], s_wk2[256], s_wv2[256];
    __shared__ __align__(16) float s_bk1[16], s_bk2[16], s_bv1[16], s_bv2[16];
    int tid = threadIdx.x;

    for (int i = tid; i < 512; i += ENB) { s_wk1[i] = wk1[i]; s_wv1[i] = wv1[i]; }
    for (int i = tid; i < 256; i += ENB) { s_wk2[i] = wk2[i]; s_wv2[i] = wv2[i]; }
    if (tid < 16) {
        s_bk1[tid] = bk1[tid]; s_bk2[tid] = bk2[tid];
        s_bv1[tid] = bv1[tid]; s_bv2[tid] = bv2[tid];
    }

    // stage this block's edge_attr coalesced
    long long e0 = (long long)blockIdx.x * ENB;
    const float4* ea4 = reinterpret_cast<const float4*>(ea) + (size_t)e0 * 8;
#pragma unroll
    for (int k = 0; k < 8; k++) {
        int f = tid + k * ENB;                  // [0, ENB*8)
        float4 v = ea4[f];
        s_ea[(f >> 3) * 9 + (f & 7)] = v;
    }
    __syncthreads();

    int e = (int)e0 + tid;
    int row, col;
    if (g_idx64) {
        const long long* p = (const long long*)ei;
        row = (int)p[e];
        col = (int)p[(size_t)EE + e];
    } else {
        row = ei[e];
        col = ei[EE + e];
    }

    // edge attrs as 16 packed f32x2
    u64 ea2[16];
#pragma unroll
    for (int q = 0; q < 8; q++) {
        float4 v = s_ea[tid * 9 + q];
        ea2[2*q]   = pack2(v.x, v.y);
        ea2[2*q+1] = pack2(v.z, v.w);
    }

    const u64* wk1p = (const u64*)s_wk1;   // row j: wk1p[j*16 + i2]
    const u64* wv1p = (const u64*)s_wv1;
    const u64* wk2p = (const u64*)s_wk2;   // row o: wk2p[o*8 + j2]
    const u64* wv2p = (const u64*)s_wv2;

    // layer 1 (shared input), lane-paired partial sums
    float tk[PH], tv[PH];
#pragma unroll
    for (int j = 0; j < PH; j++) {
        u64 ak = 0ull, av = 0ull;
#pragma unroll
        for (int i2 = 0; i2 < 16; i2++) {
            ak = ffma2(ea2[i2], wk1p[j * 16 + i2], ak);
            av = ffma2(ea2[i2], wv1p[j * 16 + i2], av);
        }
        float l, h;
        unpack2(ak, l, h); tk[j] = ssp(l + h + s_bk1[j]);
        unpack2(av, l, h); tv[j] = ssp(l + h + s_bv1[j]);
    }
    // layer 2
    u64 tk2[8], tv2[8];
#pragma unroll
    for (int j2 = 0; j2 < 8; j2++) {
        tk2[j2] = pack2(tk[2*j2], tk[2*j2+1]);
        tv2[j2] = pack2(tv[2*j2], tv[2*j2+1]);
    }
    float wkv[PH], wvv[PH];
#pragma unroll
    for (int o = 0; o < PH; o++) {
        u64 ak = 0ull, av = 0ull;
#pragma unroll
        for (int j2 = 0; j2 < 8; j2++) {
            ak = ffma2(tk2[j2], wk2p[o * 8 + j2], ak);
            av = ffma2(tv2[j2], wv2p[o * 8 + j2], av);
        }
        float l, h;
        unpack2(ak, l, h); wkv[o] = l + h + s_bk2[o];
        unpack2(av, l, h); wvv[o] = l + h + s_bv2[o];
    }
    u64 wkv2[8], wvv2[8];
#pragma unroll
    for (int q = 0; q < 8; q++) {
        wkv2[q] = pack2(wkv[2*q], wkv[2*q+1]);
        wvv2[q] = pack2(wvv[2*q], wvv[2*q+1]);
    }

    const float* Kc = g_K  + (size_t)col * HCH;
    const float* Vc = g_V  + (size_t)col * HCH;
    const float* Qt = g_Qt + (size_t)row * HCH;
    float*       Up = g_U  + (size_t)row * HCH;

    float4 qb4 = *reinterpret_cast<const float4*>(g_Qb + row * NHD);
    float qbr[4] = {qb4.x, qb4.y, qb4.z, qb4.w};

    float eh[NHD];
#pragma unroll
    for (int h = 0; h < NHD; h++) {
        u64 kr2[8], qr2[8];
        ld16p(Kc + h * PH, kr2);
        ld16p(Qt + h * PH, qr2);
        u64 acc = 0ull;
#pragma unroll
        for (int i2 = 0; i2 < 8; i2++)
            acc = ffma2(wkv2[i2], fmul2(kr2[i2], qr2[i2]), acc);
        float l, hh;
        unpack2(acc, l, hh);
        eh[h] = __expf(l + hh + qbr[h]);
    }
    red_add4(&g_D[row * NHD], eh[0], eh[1], eh[2], eh[3]);

#pragma unroll
    for (int h = 0; h < NHD; h++) {
        u64 vr2[8];
        ld16p(Vc + h * PH, vr2);
        u64 eh2 = pack2(eh[h], eh[h]);
#pragma unroll
        for (int q = 0; q < 4; q++) {
            u64 p0 = fmul2(fmul2(wvv2[2*q],   vr2[2*q]),   eh2);
            u64 p1 = fmul2(fmul2(wvv2[2*q+1], vr2[2*q+1]), eh2);
            float a, b, c, d;
            unpack2(p0, a, b); unpack2(p1, c, d);
            red_add4(Up + h * PH + 4 * q, a, b, c, d);
        }
    }
}

// ---------------------------------------------------------------------------
// Kernel 3 (fused): per block 32 nodes, 256 threads = (64 o-lanes, 4 groups).
// Per-thread weight rows live in REGISTERS; x/U/t tiles in shared, all inner
// reads warp-uniform broadcast float4. No cross-node coupling -> fully fused.
// ---------------------------------------------------------------------------
#define ANB 32
__global__ __launch_bounds__(256)
void k_out(const float* __restrict__ x,
           const float* __restrict__ wvlw, const float* __restrict__ wvlb,
           const float* __restrict__ cenw, const float* __restrict__ cenb,
           const float* __restrict__ outw, const float* __restrict__ outb,
           float* __restrict__ y) {
    __shared__ __align__(16) float s_x[ANB * 68];
    __shared__ __align__(16) float s_u[ANB * 68];
    __shared__ __align__(16) float s_t[ANB * 68];
    __shared__ float s_d[ANB * NHD];

    int tid = threadIdx.x;
    int o = tid & 63, g = tid >> 6;        // g in [0,4)
    int n0 = blockIdx.x * ANB;

    // stage x and U tiles coalesced (float4): 32 nodes x 16 float4 each
#pragma unroll
    for (int f = tid; f < ANB * 16; f += 256) {
        int r = f >> 4, c = f & 15;
        int n = n0 + r;
        float4 vx = make_float4(0.f, 0.f, 0.f, 0.f), vu = vx;
        if (n < NN) {
            vx = reinterpret_cast<const float4*>(x)[(size_t)n * 16 + c];
            vu = reinterpret_cast<const float4*>(g_U)[(size_t)n * 16 + c];
        }
        *(float4*)&s_x[r * 68 + c * 4] = vx;
        *(float4*)&s_u[r * 68 + c * 4] = vu;
    }
    if (tid < ANB * NHD) {
        int r = tid >> 2, hh = tid & 3;
        int n = n0 + r;
        s_d[tid] = (n < NN) ? g_D[n * NHD + hh] : 0.f;
    }

    // per-thread weight rows into registers
    int h = o >> 4, oo = o & 15;
    float4 wc[16], wo[16], wl[4];
#pragma unroll
    for (int q = 0; q < 16; q++) {
        wc[q] = reinterpret_cast<const float4*>(cenw)[o * 16 + q];
        wo[q] = reinterpret_cast<const float4*>(outw)[o * 16 + q];
    }
#pragma unroll
    for (int q = 0; q < 4; q++)
        wl[q] = reinterpret_cast<const float4*>(wvlw)[oo * 4 + q];
    float cb = cenb[o], ob = outb[o], vb = wvlb[oo];
    __syncthreads();

    // phase A: t = ssp(cen@x + cb + aggr) for this group's nodes
    for (int r = g; r < ANB; r += 4) {
        if (n0 + r >= NN) break;
        const float* ur = &s_u[r * 68 + h * 16];
        float acc = 0.f;
#pragma unroll
        for (int q = 0; q < 4; q++) {
            float4 u4 = *(const float4*)&ur[4 * q];
            acc += wl[q].x * u4.x + wl[q].y * u4.y + wl[q].z * u4.z + wl[q].w * u4.w;
        }
        float d = s_d[r * NHD + h];
        float aggr = (d > 0.f) ? (acc / d + vb) : 0.f;

        const float* xr = &s_x[r * 68];
        float c = cb;
#pragma unroll
        for (int q = 0; q < 16; q++) {
            float4 x4 = *(const float4*)&xr[4 * q];
            c += wc[q].x * x4.x + wc[q].y * x4.y + wc[q].z * x4.z + wc[q].w * x4.w;
        }
        s_t[r * 68 + o] = ssp(c + aggr);
    }
    __syncthreads();

    // phase B: y = out @ t + ob, direct coalesced store
    for (int r = g; r < ANB; r += 4) {
        int n = n0 + r;
        if (n >= NN) break;
        const float* tr = &s_t[r * 68];
        float a = ob;
#pragma unroll
        for (int q = 0; q < 16; q++) {
            float4 t4 = *(const float4*)&tr[4 * q];
            a += wo[q].x * t4.x + wo[q].y * t4.y + wo[q].z * t4.z + wo[q].w * t4.w;
        }
        y[(size_t)n * HCH + o] = a;
    }
}

// ---------------------------------------------------------------------------
extern "C" void kernel_launch(void* const* d_in, const int* in_sizes, int n_in,
                              void* d_out, int out_size) {
    const float* x    = (const float*)d_in[0];
    const int*   ei   = (const int*)d_in[1];
    const float* ea   = (const float*)d_in[2];
    const float* kw   = (const float*)d_in[3];
    const float* qw   = (const float*)d_in[4];
    const float* vw   = (const float*)d_in[5];
    const float* wk1  = (const float*)d_in[6];
    const float* bk1  = (const float*)d_in[7];
    const float* wk2  = (const float*)d_in[8];
    const float* bk2  = (const float*)d_in[9];
    const float* wklw = (const float*)d_in[10];
    const float* wklb = (const float*)d_in[11];
    const float* wv1  = (const float*)d_in[12];
    const float* bv1  = (const float*)d_in[13];
    const float* wv2  = (const float*)d_in[14];
    const float* bv2  = (const float*)d_in[15];
    const float* wvlw = (const float*)d_in[16];
    const float* wvlb = (const float*)d_in[17];
    const float* cenw = (const float*)d_in[18];
    const float* cenb = (const float*)d_in[19];
    const float* outw = (const float*)d_in[20];
    const float* outb = (const float*)d_in[21];
    float* out = (float*)d_out;

    k_detect<<<1, 256>>>(ei);
    k_nodes<<<(NN * NHD + 255) / 256, 256>>>(x, kw, qw, vw, wklw, wklb);
    k_edges<<<EE / ENB, ENB>>>(ei, ea, wk1, bk1, wk2, bk2,
                               wv1, bv1, wv2, bv2);
    k_out<<<(NN + ANB - 1) / ANB, 256>>>(x, wvlw, wvlb, cenw, cenb,
                                         outw, outb, out);
}

// round 9
// speedup vs baseline: 1.4189x; 1.2337x over previous
#include <cuda_runtime.h>
#include <cuda_fp16.h>

#define NN 50000
#define EE 800000
#define HCH 64
#define ECH 32
#define NHD 4
#define PH 16

typedef unsigned long long u64;

// Scratch (device globals; no allocation allowed). 16B-aligned.
// Per-node fp16 record: KV[n] = 4 heads x (K 16 | V 16) halves = 128 halves.
__device__ __align__(16) __half g_KV [NN * 128];  // col-gathered
__device__ __align__(16) __half g_Qth[NN * 64];   // row-gathered  q~ = wkl^T q
__device__ __align__(16) float  g_Qb[NN * NHD];   // q . wkl_b
__device__ __align__(16) float  g_U [NN * HCH];   // atomic accum (f32)
__device__ __align__(16) float  g_D [NN * NHD];   // atomic accum (f32)
__device__ int g_idx64;

__device__ __forceinline__ float ssp(float v) {
    return fmaxf(v, 0.f) + log1pf(__expf(-fabsf(v))) - 0.69314718055994531f;
}

// ---- packed f32x2 helpers (sm_103a) ----
__device__ __forceinline__ u64 pack2(float lo, float hi) {
    u64 d; asm("mov.b64 %0, {%1, %2};" : "=l"(d) : "f"(lo), "f"(hi)); return d;
}
__device__ __forceinline__ void unpack2(u64 a, float& lo, float& hi) {
    asm("mov.b64 {%0, %1}, %2;" : "=f"(lo), "=f"(hi) : "l"(a));
}
__device__ __forceinline__ u64 ffma2(u64 a, u64 b, u64 c) {
    u64 d; asm("fma.rn.f32x2 %0, %1, %2, %3;" : "=l"(d) : "l"(a), "l"(b), "l"(c)); return d;
}
__device__ __forceinline__ u64 fmul2(u64 a, u64 b) {
    u64 d; asm("mul.rn.f32x2 %0, %1, %2;" : "=l"(d) : "l"(a), "l"(b)); return d;
}

// convert uint4 (8 halves) -> 4 packed f32x2
__device__ __forceinline__ void cvt8(uint4 r, u64* out) {
    const __half2* h = reinterpret_cast<const __half2*>(&r);
#pragma unroll
    for (int i = 0; i < 4; i++) {
        float2 f = __half22float2(h[i]);
        out[i] = pack2(f.x, f.y);
    }
}

__device__ __forceinline__ void ld16(const float* __restrict__ p, float* r) {
#pragma unroll
    for (int i = 0; i < 4; i++) {
        float4 v = reinterpret_cast<const float4*>(p)[i];
        r[4*i+0] = v.x; r[4*i+1] = v.y; r[4*i+2] = v.z; r[4*i+3] = v.w;
    }
}

__device__ __forceinline__ uint4 toh8(const float* r) {
    uint4 o;
    __half2* h = reinterpret_cast<__half2*>(&o);
#pragma unroll
    for (int i = 0; i < 4; i++)
        h[i] = __float22half2_rn(make_float2(r[2*i], r[2*i+1]));
    return o;
}

__device__ __forceinline__ void red_add4(float* p, float a, float b, float c, float d) {
    asm volatile("red.global.add.v4.f32 [%0], {%1,%2,%3,%4};"
                 :: "l"(__cvta_generic_to_global(p)),
                    "f"(a), "f"(b), "f"(c), "f"(d) : "memory");
}

// ---------------------------------------------------------------------------
// Kernel 0: detect edge_index width.
// ---------------------------------------------------------------------------
__global__ void k_detect(const int* __restrict__ ei_w) {
    int bad = __syncthreads_or(ei_w[2 * threadIdx.x + 1] != 0);
    if (threadIdx.x == 0) g_idx64 = bad ? 0 : 1;
}

// ---------------------------------------------------------------------------
// Kernel 1: per-(node, head) precompute K, V (fp16, interleaved), Qt (fp16),
// qb (f32); zero accumulators.
// ---------------------------------------------------------------------------
__global__ __launch_bounds__(256)
void k_nodes(const float* __restrict__ x,
             const float* __restrict__ kw, const float* __restrict__ qw,
             const float* __restrict__ vw,
             const float* __restrict__ wklw, const float* __restrict__ wklb) {
    __shared__ __align__(16) float s_k[1024], s_q[1024], s_v[1024], s_l[256], s_lb[16];
    for (int i = threadIdx.x; i < 1024; i += 256) {
        s_k[i] = kw[i]; s_q[i] = qw[i]; s_v[i] = vw[i];
    }
    if (threadIdx.x < 256) s_l[threadIdx.x] = wklw[threadIdx.x];
    if (threadIdx.x < 16)  s_lb[threadIdx.x] = wklb[threadIdx.x];
    __syncthreads();

    int t = blockIdx.x * 256 + threadIdx.x;
    if (t >= NN * NHD) return;
    int n = t >> 2, h = t & 3;

    float xv[PH];
    ld16(x + (size_t)n * HCH + h * PH, xv);

    const float4* wkh = (const float4*)(s_k + h * 256);
    const float4* wqh = (const float4*)(s_q + h * 256);
    const float4* wvh = (const float4*)(s_v + h * 256);

    float kk[PH], vv[PH], qq[PH];
#pragma unroll
    for (int o = 0; o < PH; o++) {
        float a = 0.f, b = 0.f, c = 0.f;
#pragma unroll
        for (int q = 0; q < 4; q++) {
            float4 wk = wkh[o * 4 + q];
            float4 wq = wqh[o * 4 + q];
            float4 wv = wvh[o * 4 + q];
            a += xv[4*q]*wk.x + xv[4*q+1]*wk.y + xv[4*q+2]*wk.z + xv[4*q+3]*wk.w;
            b += xv[4*q]*wq.x + xv[4*q+1]*wq.y + xv[4*q+2]*wq.z + xv[4*q+3]*wq.w;
            c += xv[4*q]*wv.x + xv[4*q+1]*wv.y + xv[4*q+2]*wv.z + xv[4*q+3]*wv.w;
        }
        kk[o] = a; qq[o] = b; vv[o] = c;
    }

    float qt[PH];
#pragma unroll
    for (int i = 0; i < PH; i++) {
        float a = 0.f;
#pragma unroll
        for (int o = 0; o < PH; o++) a += qq[o] * s_l[o * PH + i];
        qt[i] = a;
    }
    float qb = 0.f;
#pragma unroll
    for (int o = 0; o < PH; o++) qb += qq[o] * s_lb[o];

    // store fp16: KV record (K then V per head), Qt record
    uint4* kvb = reinterpret_cast<uint4*>(g_KV + (size_t)n * 128);
    kvb[h * 4 + 0] = toh8(kk);
    kvb[h * 4 + 1] = toh8(kk + 8);
    kvb[h * 4 + 2] = toh8(vv);
    kvb[h * 4 + 3] = toh8(vv + 8);
    uint4* qtb = reinterpret_cast<uint4*>(g_Qth + (size_t)n * 64);
    qtb[h * 2 + 0] = toh8(qt);
    qtb[h * 2 + 1] = toh8(qt + 8);
    g_Qb[t] = qb;

    float4 z = make_float4(0.f, 0.f, 0.f, 0.f);
#pragma unroll
    for (int i = 0; i < 4; i++)
        reinterpret_cast<float4*>(g_U + (size_t)t * PH)[i] = z;
    g_D[t] = 0.f;
}

// ---------------------------------------------------------------------------
// Kernel 2: single edge pass, thread-per-edge. fp16 gathers (half traffic),
// packed f32x2 MLP math, fused red.v4 accumulation.
// ---------------------------------------------------------------------------
#define ENB 128
__global__ __launch_bounds__(ENB)
void k_edges(const int* __restrict__ ei, const float* __restrict__ ea,
             const float* __restrict__ wk1, const float* __restrict__ bk1,
             const float* __restrict__ wk2, const float* __restrict__ bk2,
             const float* __restrict__ wv1, const float* __restrict__ bv1,
             const float* __restrict__ wv2, const float* __restrict__ bv2) {
    __shared__ __align__(16) float4 s_ea[ENB * 9];
    __shared__ __align__(16) float s_wk1[512], s_wv1[512], s_wk2[256], s_wv2[256];
    __shared__ __align__(16) float s_bk1[16], s_bk2[16], s_bv1[16], s_bv2[16];
    int tid = threadIdx.x;

    for (int i = tid; i < 512; i += ENB) { s_wk1[i] = wk1[i]; s_wv1[i] = wv1[i]; }
    for (int i = tid; i < 256; i += ENB) { s_wk2[i] = wk2[i]; s_wv2[i] = wv2[i]; }
    if (tid < 16) {
        s_bk1[tid] = bk1[tid]; s_bk2[tid] = bk2[tid];
        s_bv1[tid] = bv1[tid]; s_bv2[tid] = bv2[tid];
    }

    long long e0 = (long long)blockIdx.x * ENB;
    const float4* ea4 = reinterpret_cast<const float4*>(ea) + (size_t)e0 * 8;
#pragma unroll
    for (int k = 0; k < 8; k++) {
        int f = tid + k * ENB;
        float4 v = ea4[f];
        s_ea[(f >> 3) * 9 + (f & 7)] = v;
    }
    __syncthreads();

    int e = (int)e0 + tid;
    int row, col;
    if (g_idx64) {
        const long long* p = (const long long*)ei;
        row = (int)p[e];
        col = (int)p[(size_t)EE + e];
    } else {
        row = ei[e];
        col = ei[EE + e];
    }

    u64 ea2[16];
#pragma unroll
    for (int q = 0; q < 8; q++) {
        float4 v = s_ea[tid * 9 + q];
        ea2[2*q]   = pack2(v.x, v.y);
        ea2[2*q+1] = pack2(v.z, v.w);
    }

    const u64* wk1p = (const u64*)s_wk1;
    const u64* wv1p = (const u64*)s_wv1;
    const u64* wk2p = (const u64*)s_wk2;
    const u64* wv2p = (const u64*)s_wv2;

    float tk[PH], tv[PH];
#pragma unroll
    for (int j = 0; j < PH; j++) {
        u64 ak = 0ull, av = 0ull;
#pragma unroll
        for (int i2 = 0; i2 < 16; i2++) {
            ak = ffma2(ea2[i2], wk1p[j * 16 + i2], ak);
            av = ffma2(ea2[i2], wv1p[j * 16 + i2], av);
        }
        float l, h;
        unpack2(ak, l, h); tk[j] = ssp(l + h + s_bk1[j]);
        unpack2(av, l, h); tv[j] = ssp(l + h + s_bv1[j]);
    }
    u64 tk2[8], tv2[8];
#pragma unroll
    for (int j2 = 0; j2 < 8; j2++) {
        tk2[j2] = pack2(tk[2*j2], tk[2*j2+1]);
        tv2[j2] = pack2(tv[2*j2], tv[2*j2+1]);
    }
    float wkv[PH], wvv[PH];
#pragma unroll
    for (int o = 0; o < PH; o++) {
        u64 ak = 0ull, av = 0ull;
#pragma unroll
        for (int j2 = 0; j2 < 8; j2++) {
            ak = ffma2(tk2[j2], wk2p[o * 8 + j2], ak);
            av = ffma2(tv2[j2], wv2p[o * 8 + j2], av);
        }
        float l, h;
        unpack2(ak, l, h); wkv[o] = l + h + s_bk2[o];
        unpack2(av, l, h); wvv[o] = l + h + s_bv2[o];
    }
    u64 wkv2[8], wvv2[8];
#pragma unroll
    for (int q = 0; q < 8; q++) {
        wkv2[q] = pack2(wkv[2*q], wkv[2*q+1]);
        wvv2[q] = pack2(wvv[2*q], wvv[2*q+1]);
    }

    // fp16 gathers: col KV record (16 uint4), row Qt record (8 uint4), qb
    const uint4* kvb = reinterpret_cast<const uint4*>(g_KV)  + (size_t)col * 16;
    const uint4* qtb = reinterpret_cast<const uint4*>(g_Qth) + (size_t)row * 8;
    float*       Up  = g_U + (size_t)row * HCH;

    float4 qb4 = *reinterpret_cast<const float4*>(g_Qb + row * NHD);
    float qbr[4] = {qb4.x, qb4.y, qb4.z, qb4.w};

    float eh[NHD];
#pragma unroll
    for (int h = 0; h < NHD; h++) {
        u64 k2[8], q2[8];
        cvt8(kvb[h * 4 + 0], k2);
        cvt8(kvb[h * 4 + 1], k2 + 4);
        cvt8(qtb[h * 2 + 0], q2);
        cvt8(qtb[h * 2 + 1], q2 + 4);
        u64 acc = 0ull;
#pragma unroll
        for (int i2 = 0; i2 < 8; i2++)
            acc = ffma2(wkv2[i2], fmul2(k2[i2], q2[i2]), acc);
        float l, hh;
        unpack2(acc, l, hh);
        eh[h] = __expf(l + hh + qbr[h]);
    }
    red_add4(&g_D[row * NHD], eh[0], eh[1], eh[2], eh[3]);

#pragma unroll
    for (int h = 0; h < NHD; h++) {
        u64 v2[8];
        cvt8(kvb[h * 4 + 2], v2);
        cvt8(kvb[h * 4 + 3], v2 + 4);
        u64 eh2 = pack2(eh[h], eh[h]);
#pragma unroll
        for (int q = 0; q < 4; q++) {
            u64 p0 = fmul2(fmul2(wvv2[2*q],   v2[2*q]),   eh2);
            u64 p1 = fmul2(fmul2(wvv2[2*q+1], v2[2*q+1]), eh2);
            float a, b, c, d;
            unpack2(p0, a, b); unpack2(p1, c, d);
            red_add4(Up + h * PH + 4 * q, a, b, c, d);
        }
    }
}

// ---------------------------------------------------------------------------
// Kernel 3 (fused): 48 nodes/block, 256 threads = (64 o-lanes, 4 groups).
// Weight rows in registers with PHASE-LOCAL reuse (cen rows, then the SAME
// array is overwritten with out rows) -> ~half the register footprint of R8.
// ---------------------------------------------------------------------------
#define ANB 48
__global__ __launch_bounds__(256)
void k_out(const float* __restrict__ x,
           const float* __restrict__ wvlw, const float* __restrict__ wvlb,
           const float* __restrict__ cenw, const float* __restrict__ cenb,
           const float* __restrict__ outw, const float* __restrict__ outb,
           float* __restrict__ y) {
    __shared__ __align__(16) float s_x[ANB * 68];
    __shared__ __align__(16) float s_u[ANB * 68];
    __shared__ __align__(16) float s_t[ANB * 68];
    __shared__ __align__(16) float s_wvl[256];
    __shared__ float s_d[ANB * NHD];

    int tid = threadIdx.x;
    int o = tid & 63, g = tid >> 6;
    int n0 = blockIdx.x * ANB;

    for (int f = tid; f < ANB * 16; f += 256) {
        int r = f >> 4, c = f & 15;
        int n = n0 + r;
        float4 vx = make_float4(0.f, 0.f, 0.f, 0.f), vu = vx;
        if (n < NN) {
            vx = reinterpret_cast<const float4*>(x)[(size_t)n * 16 + c];
            vu = reinterpret_cast<const float4*>(g_U)[(size_t)n * 16 + c];
        }
        *(float4*)&s_x[r * 68 + c * 4] = vx;
        *(float4*)&s_u[r * 68 + c * 4] = vu;
    }
    if (tid < ANB * NHD) {
        int r = tid >> 2, hh = tid & 3;
        int n = n0 + r;
        s_d[tid] = (n < NN) ? g_D[n * NHD + hh] : 0.f;
    }
    if (tid < 256) s_wvl[tid] = wvlw[tid];

    int h = o >> 4, oo = o & 15;
    float4 w[16];
#pragma unroll
    for (int q = 0; q < 16; q++)
        w[q] = reinterpret_cast<const float4*>(cenw)[o * 16 + q];
    float cb = cenb[o], ob = outb[o], vb = wvlb[oo];
    __syncthreads();

    // phase A: t = ssp(cen@x + cb + aggr)
    const float4* wvl4 = (const float4*)s_wvl;
    for (int r = g; r < ANB; r += 4) {
        if (n0 + r >= NN) break;
        const float* ur = &s_u[r * 68 + h * 16];
        float acc = 0.f;
#pragma unroll
        for (int q = 0; q < 4; q++) {
            float4 wl = wvl4[oo * 4 + q];
            float4 u4 = *(const float4*)&ur[4 * q];
            acc += wl.x * u4.x + wl.y * u4.y + wl.z * u4.z + wl.w * u4.w;
        }
        float d = s_d[r * NHD + h];
        float aggr = (d > 0.f) ? (acc / d + vb) : 0.f;

        const float* xr = &s_x[r * 68];
        float c = cb;
#pragma unroll
        for (int q = 0; q < 16; q++) {
            float4 x4 = *(const float4*)&xr[4 * q];
            c += w[q].x * x4.x + w[q].y * x4.y + w[q].z * x4.z + w[q].w * x4.w;
        }
        s_t[r * 68 + o] = ssp(c + aggr);
    }
    __syncthreads();

    // reload the SAME register array with out rows (phase-local live range)
#pragma unroll
    for (int q = 0; q < 16; q++)
        w[q] = reinterpret_cast<const float4*>(outw)[o * 16 + q];

    // phase B: y = out @ t + ob
    for (int r = g; r < ANB; r += 4) {
        int n = n0 + r;
        if (n >= NN) break;
        const float* tr = &s_t[r * 68];
        float a = ob;
#pragma unroll
        for (int q = 0; q < 16; q++) {
            float4 t4 = *(const float4*)&tr[4 * q];
            a += w[q].x * t4.x + w[q].y * t4.y + w[q].z * t4.z + w[q].w * t4.w;
        }
        y[(size_t)n * HCH + o] = a;
    }
}

// ---------------------------------------------------------------------------
extern "C" void kernel_launch(void* const* d_in, const int* in_sizes, int n_in,
                              void* d_out, int out_size) {
    const float* x    = (const float*)d_in[0];
    const int*   ei   = (const int*)d_in[1];
    const float* ea   = (const float*)d_in[2];
    const float* kw   = (const float*)d_in[3];
    const float* qw   = (const float*)d_in[4];
    const float* vw   = (const float*)d_in[5];
    const float* wk1  = (const float*)d_in[6];
    const float* bk1  = (const float*)d_in[7];
    const float* wk2  = (const float*)d_in[8];
    const float* bk2  = (const float*)d_in[9];
    const float* wklw = (const float*)d_in[10];
    const float* wklb = (const float*)d_in[11];
    const float* wv1  = (const float*)d_in[12];
    const float* bv1  = (const float*)d_in[13];
    const float* wv2  = (const float*)d_in[14];
    const float* bv2  = (const float*)d_in[15];
    const float* wvlw = (const float*)d_in[16];
    const float* wvlb = (const float*)d_in[17];
    const float* cenw = (const float*)d_in[18];
    const float* cenb = (const float*)d_in[19];
    const float* outw = (const float*)d_in[20];
    const float* outb = (const float*)d_in[21];
    float* out = (float*)d_out;

    k_detect<<<1, 256>>>(ei);
    k_nodes<<<(NN * NHD + 255) / 256, 256>>>(x, kw, qw, vw, wklw, wklb);
    k_edges<<<EE / ENB, ENB>>>(ei, ea, wk1, bk1, wk2, bk2,
                               wv1, bv1, wv2, bv2);
    k_out<<<(NN + ANB - 1) / ANB, 256>>>(x, wvlw, wvlb, cenw, cenb,
                                         outw, outb, out);
}

// round 10
// speedup vs baseline: 1.6494x; 1.1625x over previous
#include <cuda_runtime.h>
#include <cuda_fp16.h>

#define NN 50000
#define EE 800000
#define HCH 64
#define ECH 32
#define NHD 4
#define PH 16

typedef unsigned long long u64;

// Scratch (device globals). Records laid out for gather coalescing:
//  g_KV[n]  : [K h0..h3 | V h0..h3]  = 256B (fp16) ; 4 head-lanes -> 1 line
//  g_Qth[n] : [Qt h0..h3]            = 128B (fp16)
//  g_Wk/g_Wv: per-edge MLP outputs   = 32B each (fp16)
__device__ __align__(16) __half g_KV [NN * 128];
__device__ __align__(16) __half g_Qth[NN * 64];
__device__ __align__(16) float  g_Qb[NN * NHD];
__device__ __align__(16) __half g_Wk[(size_t)EE * 16];
__device__ __align__(16) __half g_Wv[(size_t)EE * 16];
__device__ __align__(16) float  g_U [NN * HCH];
__device__ __align__(16) float  g_D [NN * NHD];
__device__ int g_idx64;

__device__ __forceinline__ float ssp(float v) {
    return fmaxf(v, 0.f) + log1pf(__expf(-fabsf(v))) - 0.69314718055994531f;
}

// ---- packed f32x2 helpers (sm_103a) ----
__device__ __forceinline__ u64 pack2(float lo, float hi) {
    u64 d; asm("mov.b64 %0, {%1, %2};" : "=l"(d) : "f"(lo), "f"(hi)); return d;
}
__device__ __forceinline__ void unpack2(u64 a, float& lo, float& hi) {
    asm("mov.b64 {%0, %1}, %2;" : "=f"(lo), "=f"(hi) : "l"(a));
}
__device__ __forceinline__ u64 ffma2(u64 a, u64 b, u64 c) {
    u64 d; asm("fma.rn.f32x2 %0, %1, %2, %3;" : "=l"(d) : "l"(a), "l"(b), "l"(c)); return d;
}
__device__ __forceinline__ u64 fmul2(u64 a, u64 b) {
    u64 d; asm("mul.rn.f32x2 %0, %1, %2;" : "=l"(d) : "l"(a), "l"(b)); return d;
}

// uint4 (8 halves) -> 4 packed f32x2
__device__ __forceinline__ void cvt8(uint4 r, u64* out) {
    const __half2* h = reinterpret_cast<const __half2*>(&r);
#pragma unroll
    for (int i = 0; i < 4; i++) {
        float2 f = __half22float2(h[i]);
        out[i] = pack2(f.x, f.y);
    }
}

__device__ __forceinline__ void ld16(const float* __restrict__ p, float* r) {
#pragma unroll
    for (int i = 0; i < 4; i++) {
        float4 v = reinterpret_cast<const float4*>(p)[i];
        r[4*i+0] = v.x; r[4*i+1] = v.y; r[4*i+2] = v.z; r[4*i+3] = v.w;
    }
}

__device__ __forceinline__ uint4 toh8(const float* r) {
    uint4 o;
    __half2* h = reinterpret_cast<__half2*>(&o);
#pragma unroll
    for (int i = 0; i < 4; i++)
        h[i] = __float22half2_rn(make_float2(r[2*i], r[2*i+1]));
    return o;
}

__device__ __forceinline__ void red_add4(float* p, float a, float b, float c, float d) {
    asm volatile("red.global.add.v4.f32 [%0], {%1,%2,%3,%4};"
                 :: "l"(__cvta_generic_to_global(p)),
                    "f"(a), "f"(b), "f"(c), "f"(d) : "memory");
}
__device__ __forceinline__ void red_add1(float* p, float a) {
    asm volatile("red.global.add.f32 [%0], %1;"
                 :: "l"(__cvta_generic_to_global(p)), "f"(a) : "memory");
}

// ---------------------------------------------------------------------------
__global__ void k_detect(const int* __restrict__ ei_w) {
    int bad = __syncthreads_or(ei_w[2 * threadIdx.x + 1] != 0);
    if (threadIdx.x == 0) g_idx64 = bad ? 0 : 1;
}

// ---------------------------------------------------------------------------
// Kernel 1: node precompute (K,V,Qt fp16 records; qb f32; zero accumulators)
// ---------------------------------------------------------------------------
__global__ __launch_bounds__(256)
void k_nodes(const float* __restrict__ x,
             const float* __restrict__ kw, const float* __restrict__ qw,
             const float* __restrict__ vw,
             const float* __restrict__ wklw, const float* __restrict__ wklb) {
    __shared__ __align__(16) float s_k[1024], s_q[1024], s_v[1024], s_l[256], s_lb[16];
    for (int i = threadIdx.x; i < 1024; i += 256) {
        s_k[i] = kw[i]; s_q[i] = qw[i]; s_v[i] = vw[i];
    }
    if (threadIdx.x < 256) s_l[threadIdx.x] = wklw[threadIdx.x];
    if (threadIdx.x < 16)  s_lb[threadIdx.x] = wklb[threadIdx.x];
    __syncthreads();

    int t = blockIdx.x * 256 + threadIdx.x;
    if (t >= NN * NHD) return;
    int n = t >> 2, h = t & 3;

    float xv[PH];
    ld16(x + (size_t)n * HCH + h * PH, xv);

    const float4* wkh = (const float4*)(s_k + h * 256);
    const float4* wqh = (const float4*)(s_q + h * 256);
    const float4* wvh = (const float4*)(s_v + h * 256);

    float kk[PH], vv[PH], qq[PH];
#pragma unroll
    for (int o = 0; o < PH; o++) {
        float a = 0.f, b = 0.f, c = 0.f;
#pragma unroll
        for (int q = 0; q < 4; q++) {
            float4 wk = wkh[o * 4 + q];
            float4 wq = wqh[o * 4 + q];
            float4 wv = wvh[o * 4 + q];
            a += xv[4*q]*wk.x + xv[4*q+1]*wk.y + xv[4*q+2]*wk.z + xv[4*q+3]*wk.w;
            b += xv[4*q]*wq.x + xv[4*q+1]*wq.y + xv[4*q+2]*wq.z + xv[4*q+3]*wq.w;
            c += xv[4*q]*wv.x + xv[4*q+1]*wv.y + xv[4*q+2]*wv.z + xv[4*q+3]*wv.w;
        }
        kk[o] = a; qq[o] = b; vv[o] = c;
    }

    float qt[PH];
#pragma unroll
    for (int i = 0; i < PH; i++) {
        float a = 0.f;
#pragma unroll
        for (int o = 0; o < PH; o++) a += qq[o] * s_l[o * PH + i];
        qt[i] = a;
    }
    float qb = 0.f;
#pragma unroll
    for (int o = 0; o < PH; o++) qb += qq[o] * s_lb[o];

    // K block then V block (head-contiguous for 1-line gathers)
    uint4* kvb = reinterpret_cast<uint4*>(g_KV + (size_t)n * 128);
    kvb[h * 2 + 0] = toh8(kk);
    kvb[h * 2 + 1] = toh8(kk + 8);
    kvb[8 + h * 2 + 0] = toh8(vv);
    kvb[8 + h * 2 + 1] = toh8(vv + 8);
    uint4* qtb = reinterpret_cast<uint4*>(g_Qth + (size_t)n * 64);
    qtb[h * 2 + 0] = toh8(qt);
    qtb[h * 2 + 1] = toh8(qt + 8);
    g_Qb[t] = qb;

    float4 z = make_float4(0.f, 0.f, 0.f, 0.f);
#pragma unroll
    for (int i = 0; i < 4; i++)
        reinterpret_cast<float4*>(g_U + (size_t)t * PH)[i] = z;
    g_D[t] = 0.f;
}

// ---------------------------------------------------------------------------
// Kernel 2a: dense per-edge MLPs (NO gathers) -> W_k, W_v fp16.
// ---------------------------------------------------------------------------
#define MNB 256
__global__ __launch_bounds__(MNB)
void k_mlp(const float* __restrict__ ea,
           const float* __restrict__ wk1, const float* __restrict__ bk1,
           const float* __restrict__ wk2, const float* __restrict__ bk2,
           const float* __restrict__ wv1, const float* __restrict__ bv1,
           const float* __restrict__ wv2, const float* __restrict__ bv2) {
    __shared__ __align__(16) float4 s_ea[MNB * 9];
    __shared__ __align__(16) float s_wk1[512], s_wv1[512], s_wk2[256], s_wv2[256];
    __shared__ __align__(16) float s_bk1[16], s_bk2[16], s_bv1[16], s_bv2[16];
    int tid = threadIdx.x;

    for (int i = tid; i < 512; i += MNB) { s_wk1[i] = wk1[i]; s_wv1[i] = wv1[i]; }
    for (int i = tid; i < 256; i += MNB) { s_wk2[i] = wk2[i]; s_wv2[i] = wv2[i]; }
    if (tid < 16) {
        s_bk1[tid] = bk1[tid]; s_bk2[tid] = bk2[tid];
        s_bv1[tid] = bv1[tid]; s_bv2[tid] = bv2[tid];
    }

    long long e0 = (long long)blockIdx.x * MNB;
    const float4* ea4 = reinterpret_cast<const float4*>(ea) + (size_t)e0 * 8;
#pragma unroll
    for (int k = 0; k < 8; k++) {
        int f = tid + k * MNB;
        float4 v = ea4[f];
        s_ea[(f >> 3) * 9 + (f & 7)] = v;
    }
    __syncthreads();

    u64 ea2[16];
#pragma unroll
    for (int q = 0; q < 8; q++) {
        float4 v = s_ea[tid * 9 + q];
        ea2[2*q]   = pack2(v.x, v.y);
        ea2[2*q+1] = pack2(v.z, v.w);
    }

    const u64* wk1p = (const u64*)s_wk1;
    const u64* wv1p = (const u64*)s_wv1;
    const u64* wk2p = (const u64*)s_wk2;
    const u64* wv2p = (const u64*)s_wv2;

    float tk[PH], tv[PH];
#pragma unroll
    for (int j = 0; j < PH; j++) {
        u64 ak = 0ull, av = 0ull;
#pragma unroll
        for (int i2 = 0; i2 < 16; i2++) {
            ak = ffma2(ea2[i2], wk1p[j * 16 + i2], ak);
            av = ffma2(ea2[i2], wv1p[j * 16 + i2], av);
        }
        float l, h;
        unpack2(ak, l, h); tk[j] = ssp(l + h + s_bk1[j]);
        unpack2(av, l, h); tv[j] = ssp(l + h + s_bv1[j]);
    }
    u64 tk2[8], tv2[8];
#pragma unroll
    for (int j2 = 0; j2 < 8; j2++) {
        tk2[j2] = pack2(tk[2*j2], tk[2*j2+1]);
        tv2[j2] = pack2(tv[2*j2], tv[2*j2+1]);
    }
    float wkv[PH], wvv[PH];
#pragma unroll
    for (int o = 0; o < PH; o++) {
        u64 ak = 0ull, av = 0ull;
#pragma unroll
        for (int j2 = 0; j2 < 8; j2++) {
            ak = ffma2(tk2[j2], wk2p[o * 8 + j2], ak);
            av = ffma2(tv2[j2], wv2p[o * 8 + j2], av);
        }
        float l, h;
        unpack2(ak, l, h); wkv[o] = l + h + s_bk2[o];
        unpack2(av, l, h); wvv[o] = l + h + s_bv2[o];
    }

    size_t e = (size_t)e0 + tid;
    uint4* gk = reinterpret_cast<uint4*>(g_Wk) + e * 2;
    uint4* gv = reinterpret_cast<uint4*>(g_Wv) + e * 2;
    gk[0] = toh8(wkv); gk[1] = toh8(wkv + 8);
    gv[0] = toh8(wvv); gv[1] = toh8(wvv + 8);
}

// ---------------------------------------------------------------------------
// Kernel 2b: attention gather pass, thread per (edge, head).
// 4 consecutive lanes = 4 heads of one edge -> each gather op covers one
// contiguous 128B record line. Small math, high occupancy, latency-tolerant.
// ---------------------------------------------------------------------------
__global__ __launch_bounds__(256)
void k_attn(const int* __restrict__ ei) {
    int idx = blockIdx.x * 256 + threadIdx.x;
    int e = idx >> 2, h = idx & 3;

    int row, col;
    if (g_idx64) {
        const long long* p = (const long long*)ei;
        row = (int)p[e];
        col = (int)p[(size_t)EE + e];
    } else {
        row = ei[e];
        col = ei[EE + e];
    }

    const uint4* kv  = reinterpret_cast<const uint4*>(g_KV)  + (size_t)col * 16;
    const uint4* qt  = reinterpret_cast<const uint4*>(g_Qth) + (size_t)row * 8;
    const uint4* wkp = reinterpret_cast<const uint4*>(g_Wk)  + (size_t)e * 2;

    // logit = qb + sum_i Wk[i] * K[col,h,i] * Qt[row,h,i]
    u64 wk2[8], k2[8], q2[8];
    cvt8(wkp[0], wk2); cvt8(wkp[1], wk2 + 4);
    cvt8(kv[h * 2], k2); cvt8(kv[h * 2 + 1], k2 + 4);
    cvt8(qt[h * 2], q2); cvt8(qt[h * 2 + 1], q2 + 4);

    u64 acc = 0ull;
#pragma unroll
    for (int i = 0; i < 8; i++)
        acc = ffma2(wk2[i], fmul2(k2[i], q2[i]), acc);
    float l, hh;
    unpack2(acc, l, hh);
    float eh = __expf(l + hh + g_Qb[row * NHD + h]);

    red_add1(&g_D[row * NHD + h], eh);

    // U[row,h,:] += eh * Wv * V[col,h,:]
    const uint4* wvp = reinterpret_cast<const uint4*>(g_Wv) + (size_t)e * 2;
    u64 wv2[8], v2[8];
    cvt8(wvp[0], wv2); cvt8(wvp[1], wv2 + 4);
    cvt8(kv[8 + h * 2], v2); cvt8(kv[8 + h * 2 + 1], v2 + 4);

    u64 eh2 = pack2(eh, eh);
    float* Up = g_U + (size_t)row * HCH + h * PH;
#pragma unroll
    for (int q = 0; q < 4; q++) {
        u64 p0 = fmul2(fmul2(wv2[2*q],   v2[2*q]),   eh2);
        u64 p1 = fmul2(fmul2(wv2[2*q+1], v2[2*q+1]), eh2);
        float a, b, c, d;
        unpack2(p0, a, b); unpack2(p1, c, d);
        red_add4(Up + 4 * q, a, b, c, d);
    }
}

// ---------------------------------------------------------------------------
// Kernel 3 (fused epilogue): unchanged from R9 (76us measured).
// ---------------------------------------------------------------------------
#define ANB 48
__global__ __launch_bounds__(256)
void k_out(const float* __restrict__ x,
           const float* __restrict__ wvlw, const float* __restrict__ wvlb,
           const float* __restrict__ cenw, const float* __restrict__ cenb,
           const float* __restrict__ outw, const float* __restrict__ outb,
           float* __restrict__ y) {
    __shared__ __align__(16) float s_x[ANB * 68];
    __shared__ __align__(16) float s_u[ANB * 68];
    __shared__ __align__(16) float s_t[ANB * 68];
    __shared__ __align__(16) float s_wvl[256];
    __shared__ float s_d[ANB * NHD];

    int tid = threadIdx.x;
    int o = tid & 63, g = tid >> 6;
    int n0 = blockIdx.x * ANB;

    for (int f = tid; f < ANB * 16; f += 256) {
        int r = f >> 4, c = f & 15;
        int n = n0 + r;
        float4 vx = make_float4(0.f, 0.f, 0.f, 0.f), vu = vx;
        if (n < NN) {
            vx = reinterpret_cast<const float4*>(x)[(size_t)n * 16 + c];
            vu = reinterpret_cast<const float4*>(g_U)[(size_t)n * 16 + c];
        }
        *(float4*)&s_x[r * 68 + c * 4] = vx;
        *(float4*)&s_u[r * 68 + c * 4] = vu;
    }
    if (tid < ANB * NHD) {
        int r = tid >> 2, hh = tid & 3;
        int n = n0 + r;
        s_d[tid] = (n < NN) ? g_D[n * NHD + hh] : 0.f;
    }
    if (tid < 256) s_wvl[tid] = wvlw[tid];

    int h = o >> 4, oo = o & 15;
    float4 w[16];
#pragma unroll
    for (int q = 0; q < 16; q++)
        w[q] = reinterpret_cast<const float4*>(cenw)[o * 16 + q];
    float cb = cenb[o], ob = outb[o], vb = wvlb[oo];
    __syncthreads();

    const float4* wvl4 = (const float4*)s_wvl;
    for (int r = g; r < ANB; r += 4) {
        if (n0 + r >= NN) break;
        const float* ur = &s_u[r * 68 + h * 16];
        float acc = 0.f;
#pragma unroll
        for (int q = 0; q < 4; q++) {
            float4 wl = wvl4[oo * 4 + q];
            float4 u4 = *(const float4*)&ur[4 * q];
            acc += wl.x * u4.x + wl.y * u4.y + wl.z * u4.z + wl.w * u4.w;
        }
        float d = s_d[r * NHD + h];
        float aggr = (d > 0.f) ? (acc / d + vb) : 0.f;

        const float* xr = &s_x[r * 68];
        float c = cb;
#pragma unroll
        for (int q = 0; q < 16; q++) {
            float4 x4 = *(const float4*)&xr[4 * q];
            c += w[q].x * x4.x + w[q].y * x4.y + w[q].z * x4.z + w[q].w * x4.w;
        }
        s_t[r * 68 + o] = ssp(c + aggr);
    }
    __syncthreads();

#pragma unroll
    for (int q = 0; q < 16; q++)
        w[q] = reinterpret_cast<const float4*>(outw)[o * 16 + q];

    for (int r = g; r < ANB; r += 4) {
        int n = n0 + r;
        if (n >= NN) break;
        const float* tr = &s_t[r * 68];
        float a = ob;
#pragma unroll
        for (int q = 0; q < 16; q++) {
            float4 t4 = *(const float4*)&tr[4 * q];
            a += w[q].x * t4.x + w[q].y * t4.y + w[q].z * t4.z + w[q].w * t4.w;
        }
        y[(size_t)n * HCH + o] = a;
    }
}

// ---------------------------------------------------------------------------
extern "C" void kernel_launch(void* const* d_in, const int* in_sizes, int n_in,
                              void* d_out, int out_size) {
    const float* x    = (const float*)d_in[0];
    const int*   ei   = (const int*)d_in[1];
    const float* ea   = (const float*)d_in[2];
    const float* kw   = (const float*)d_in[3];
    const float* qw   = (const float*)d_in[4];
    const float* vw   = (const float*)d_in[5];
    const float* wk1  = (const float*)d_in[6];
    const float* bk1  = (const float*)d_in[7];
    const float* wk2  = (const float*)d_in[8];
    const float* bk2  = (const float*)d_in[9];
    const float* wklw = (const float*)d_in[10];
    const float* wklb = (const float*)d_in[11];
    const float* wv1  = (const float*)d_in[12];
    const float* bv1  = (const float*)d_in[13];
    const float* wv2  = (const float*)d_in[14];
    const float* bv2  = (const float*)d_in[15];
    const float* wvlw = (const float*)d_in[16];
    const float* wvlb = (const float*)d_in[17];
    const float* cenw = (const float*)d_in[18];
    const float* cenb = (const float*)d_in[19];
    const float* outw = (const float*)d_in[20];
    const float* outb = (const float*)d_in[21];
    float* out = (float*)d_out;

    k_detect<<<1, 256>>>(ei);
    k_nodes<<<(NN * NHD + 255) / 256, 256>>>(x, kw, qw, vw, wklw, wklb);
    k_mlp<<<EE / MNB, MNB>>>(ea, wk1, bk1, wk2, bk2, wv1, bv1, wv2, bv2);
    k_attn<<<(EE * NHD) / 256, 256>>>(ei);
    k_out<<<(NN + ANB - 1) / ANB, 256>>>(x, wvlw, wvlb, cenw, cenb,
                                         outw, outb, out);
}

// round 11
// speedup vs baseline: 1.7372x; 1.0532x over previous
#include <cuda_runtime.h>
#include <cuda_fp16.h>

#define NN 50000
#define EE 800000
#define HCH 64
#define ECH 32
#define NHD 4
#define PH 16

typedef unsigned long long u64;

// Scratch (device globals). Records laid out for gather coalescing:
//  g_KV[n]  : [K h0..h3 | V h0..h3]  = 256B (fp16)
//  g_Qth[n] : [Qt h0..h3]            = 128B (fp16)
//  g_Wk/g_Wv: per-edge MLP outputs   = 32B each (fp16)
__device__ __align__(16) __half g_KV [NN * 128];
__device__ __align__(16) __half g_Qth[NN * 64];
__device__ __align__(16) float  g_Qb[NN * NHD];
__device__ __align__(16) __half g_Wk[(size_t)EE * 16];
__device__ __align__(16) __half g_Wv[(size_t)EE * 16];
__device__ __align__(16) float  g_U [NN * HCH];
__device__ __align__(16) float  g_D [NN * NHD];
__device__ int g_idx64;

// fast shifted-softplus: max(v,0) + log(0.5*exp(-|v|) + 0.5)
// (the -ln2 shift folds into the log argument; ~2 MUFU, abs err ~1e-6)
__device__ __forceinline__ float ssp(float v) {
    return fmaxf(v, 0.f) + __logf(fmaf(0.5f, __expf(-fabsf(v)), 0.5f));
}

// ---- packed f32x2 helpers (sm_103a) ----
__device__ __forceinline__ u64 pack2(float lo, float hi) {
    u64 d; asm("mov.b64 %0, {%1, %2};" : "=l"(d) : "f"(lo), "f"(hi)); return d;
}
__device__ __forceinline__ void unpack2(u64 a, float& lo, float& hi) {
    asm("mov.b64 {%0, %1}, %2;" : "=f"(lo), "=f"(hi) : "l"(a));
}
__device__ __forceinline__ u64 ffma2(u64 a, u64 b, u64 c) {
    u64 d; asm("fma.rn.f32x2 %0, %1, %2, %3;" : "=l"(d) : "l"(a), "l"(b), "l"(c)); return d;
}
__device__ __forceinline__ u64 fmul2(u64 a, u64 b) {
    u64 d; asm("mul.rn.f32x2 %0, %1, %2;" : "=l"(d) : "l"(a), "l"(b)); return d;
}

// uint4 (8 halves) -> 4 packed f32x2
__device__ __forceinline__ void cvt8(uint4 r, u64* out) {
    const __half2* h = reinterpret_cast<const __half2*>(&r);
#pragma unroll
    for (int i = 0; i < 4; i++) {
        float2 f = __half22float2(h[i]);
        out[i] = pack2(f.x, f.y);
    }
}

__device__ __forceinline__ void ld16(const float* __restrict__ p, float* r) {
#pragma unroll
    for (int i = 0; i < 4; i++) {
        float4 v = reinterpret_cast<const float4*>(p)[i];
        r[4*i+0] = v.x; r[4*i+1] = v.y; r[4*i+2] = v.z; r[4*i+3] = v.w;
    }
}

__device__ __forceinline__ uint4 toh8(const float* r) {
    uint4 o;
    __half2* h = reinterpret_cast<__half2*>(&o);
#pragma unroll
    for (int i = 0; i < 4; i++)
        h[i] = __float22half2_rn(make_float2(r[2*i], r[2*i+1]));
    return o;
}

__device__ __forceinline__ void red_add4(float* p, float a, float b, float c, float d) {
    asm volatile("red.global.add.v4.f32 [%0], {%1,%2,%3,%4};"
                 :: "l"(__cvta_generic_to_global(p)),
                    "f"(a), "f"(b), "f"(c), "f"(d) : "memory");
}
__device__ __forceinline__ void red_add1(float* p, float a) {
    asm volatile("red.global.add.f32 [%0], %1;"
                 :: "l"(__cvta_generic_to_global(p)), "f"(a) : "memory");
}

// ---------------------------------------------------------------------------
__global__ void k_detect(const int* __restrict__ ei_w) {
    int bad = __syncthreads_or(ei_w[2 * threadIdx.x + 1] != 0);
    if (threadIdx.x == 0) g_idx64 = bad ? 0 : 1;
}

// ---------------------------------------------------------------------------
// Kernel 1: node precompute (K,V,Qt fp16 records; qb f32; zero accumulators)
// ---------------------------------------------------------------------------
__global__ __launch_bounds__(256)
void k_nodes(const float* __restrict__ x,
             const float* __restrict__ kw, const float* __restrict__ qw,
             const float* __restrict__ vw,
             const float* __restrict__ wklw, const float* __restrict__ wklb) {
    __shared__ __align__(16) float s_k[1024], s_q[1024], s_v[1024], s_l[256], s_lb[16];
    for (int i = threadIdx.x; i < 1024; i += 256) {
        s_k[i] = kw[i]; s_q[i] = qw[i]; s_v[i] = vw[i];
    }
    if (threadIdx.x < 256) s_l[threadIdx.x] = wklw[threadIdx.x];
    if (threadIdx.x < 16)  s_lb[threadIdx.x] = wklb[threadIdx.x];
    __syncthreads();

    int t = blockIdx.x * 256 + threadIdx.x;
    if (t >= NN * NHD) return;
    int n = t >> 2, h = t & 3;

    float xv[PH];
    ld16(x + (size_t)n * HCH + h * PH, xv);

    const float4* wkh = (const float4*)(s_k + h * 256);
    const float4* wqh = (const float4*)(s_q + h * 256);
    const float4* wvh = (const float4*)(s_v + h * 256);

    float kk[PH], vv[PH], qq[PH];
#pragma unroll
    for (int o = 0; o < PH; o++) {
        float a = 0.f, b = 0.f, c = 0.f;
#pragma unroll
        for (int q = 0; q < 4; q++) {
            float4 wk = wkh[o * 4 + q];
            float4 wq = wqh[o * 4 + q];
            float4 wv = wvh[o * 4 + q];
            a += xv[4*q]*wk.x + xv[4*q+1]*wk.y + xv[4*q+2]*wk.z + xv[4*q+3]*wk.w;
            b += xv[4*q]*wq.x + xv[4*q+1]*wq.y + xv[4*q+2]*wq.z + xv[4*q+3]*wq.w;
            c += xv[4*q]*wv.x + xv[4*q+1]*wv.y + xv[4*q+2]*wv.z + xv[4*q+3]*wv.w;
        }
        kk[o] = a; qq[o] = b; vv[o] = c;
    }

    float qt[PH];
#pragma unroll
    for (int i = 0; i < PH; i++) {
        float a = 0.f;
#pragma unroll
        for (int o = 0; o < PH; o++) a += qq[o] * s_l[o * PH + i];
        qt[i] = a;
    }
    float qb = 0.f;
#pragma unroll
    for (int o = 0; o < PH; o++) qb += qq[o] * s_lb[o];

    uint4* kvb = reinterpret_cast<uint4*>(g_KV + (size_t)n * 128);
    kvb[h * 2 + 0] = toh8(kk);
    kvb[h * 2 + 1] = toh8(kk + 8);
    kvb[8 + h * 2 + 0] = toh8(vv);
    kvb[8 + h * 2 + 1] = toh8(vv + 8);
    uint4* qtb = reinterpret_cast<uint4*>(g_Qth + (size_t)n * 64);
    qtb[h * 2 + 0] = toh8(qt);
    qtb[h * 2 + 1] = toh8(qt + 8);
    g_Qb[t] = qb;

    float4 z = make_float4(0.f, 0.f, 0.f, 0.f);
#pragma unroll
    for (int i = 0; i < 4; i++)
        reinterpret_cast<float4*>(g_U + (size_t)t * PH)[i] = z;
    g_D[t] = 0.f;
}

// ---------------------------------------------------------------------------
// Kernel 2a: dense per-edge MLPs (NO gathers) -> W_k, W_v fp16.
// ---------------------------------------------------------------------------
#define MNB 256
__global__ __launch_bounds__(MNB)
void k_mlp(const float* __restrict__ ea,
           const float* __restrict__ wk1, const float* __restrict__ bk1,
           const float* __restrict__ wk2, const float* __restrict__ bk2,
           const float* __restrict__ wv1, const float* __restrict__ bv1,
           const float* __restrict__ wv2, const float* __restrict__ bv2) {
    __shared__ __align__(16) float4 s_ea[MNB * 9];
    __shared__ __align__(16) float s_wk1[512], s_wv1[512], s_wk2[256], s_wv2[256];
    __shared__ __align__(16) float s_bk1[16], s_bk2[16], s_bv1[16], s_bv2[16];
    int tid = threadIdx.x;

    for (int i = tid; i < 512; i += MNB) { s_wk1[i] = wk1[i]; s_wv1[i] = wv1[i]; }
    for (int i = tid; i < 256; i += MNB) { s_wk2[i] = wk2[i]; s_wv2[i] = wv2[i]; }
    if (tid < 16) {
        s_bk1[tid] = bk1[tid]; s_bk2[tid] = bk2[tid];
        s_bv1[tid] = bv1[tid]; s_bv2[tid] = bv2[tid];
    }

    long long e0 = (long long)blockIdx.x * MNB;
    const float4* ea4 = reinterpret_cast<const float4*>(ea) + (size_t)e0 * 8;
#pragma unroll
    for (int k = 0; k < 8; k++) {
        int f = tid + k * MNB;
        float4 v = ea4[f];
        s_ea[(f >> 3) * 9 + (f & 7)] = v;
    }
    __syncthreads();

    u64 ea2[16];
#pragma unroll
    for (int q = 0; q < 8; q++) {
        float4 v = s_ea[tid * 9 + q];
        ea2[2*q]   = pack2(v.x, v.y);
        ea2[2*q+1] = pack2(v.z, v.w);
    }

    const u64* wk1p = (const u64*)s_wk1;
    const u64* wv1p = (const u64*)s_wv1;
    const u64* wk2p = (const u64*)s_wk2;
    const u64* wv2p = (const u64*)s_wv2;

    float tk[PH], tv[PH];
#pragma unroll
    for (int j = 0; j < PH; j++) {
        u64 ak = 0ull, av = 0ull;
#pragma unroll
        for (int i2 = 0; i2 < 16; i2++) {
            ak = ffma2(ea2[i2], wk1p[j * 16 + i2], ak);
            av = ffma2(ea2[i2], wv1p[j * 16 + i2], av);
        }
        float l, h;
        unpack2(ak, l, h); tk[j] = ssp(l + h + s_bk1[j]);
        unpack2(av, l, h); tv[j] = ssp(l + h + s_bv1[j]);
    }
    u64 tk2[8], tv2[8];
#pragma unroll
    for (int j2 = 0; j2 < 8; j2++) {
        tk2[j2] = pack2(tk[2*j2], tk[2*j2+1]);
        tv2[j2] = pack2(tv[2*j2], tv[2*j2+1]);
    }
    float wkv[PH], wvv[PH];
#pragma unroll
    for (int o = 0; o < PH; o++) {
        u64 ak = 0ull, av = 0ull;
#pragma unroll
        for (int j2 = 0; j2 < 8; j2++) {
            ak = ffma2(tk2[j2], wk2p[o * 8 + j2], ak);
            av = ffma2(tv2[j2], wv2p[o * 8 + j2], av);
        }
        float l, h;
        unpack2(ak, l, h); wkv[o] = l + h + s_bk2[o];
        unpack2(av, l, h); wvv[o] = l + h + s_bv2[o];
    }

    size_t e = (size_t)e0 + tid;
    uint4* gk = reinterpret_cast<uint4*>(g_Wk) + e * 2;
    uint4* gv = reinterpret_cast<uint4*>(g_Wv) + e * 2;
    gk[0] = toh8(wkv); gk[1] = toh8(wkv + 8);
    gv[0] = toh8(wvv); gv[1] = toh8(wvv + 8);
}

// ---------------------------------------------------------------------------
// Kernel 2b: attention gather pass, thread per (edge, head).
// ---------------------------------------------------------------------------
__global__ __launch_bounds__(256)
void k_attn(const int* __restrict__ ei) {
    int idx = blockIdx.x * 256 + threadIdx.x;
    int e = idx >> 2, h = idx & 3;

    int row, col;
    if (g_idx64) {
        const long long* p = (const long long*)ei;
        row = (int)p[e];
        col = (int)p[(size_t)EE + e];
    } else {
        row = ei[e];
        col = ei[EE + e];
    }

    const uint4* kv  = reinterpret_cast<const uint4*>(g_KV)  + (size_t)col * 16;
    const uint4* qt  = reinterpret_cast<const uint4*>(g_Qth) + (size_t)row * 8;
    const uint4* wkp = reinterpret_cast<const uint4*>(g_Wk)  + (size_t)e * 2;

    u64 wk2[8], k2[8], q2[8];
    cvt8(wkp[0], wk2); cvt8(wkp[1], wk2 + 4);
    cvt8(kv[h * 2], k2); cvt8(kv[h * 2 + 1], k2 + 4);
    cvt8(qt[h * 2], q2); cvt8(qt[h * 2 + 1], q2 + 4);

    u64 acc = 0ull;
#pragma unroll
    for (int i = 0; i < 8; i++)
        acc = ffma2(wk2[i], fmul2(k2[i], q2[i]), acc);
    float l, hh;
    unpack2(acc, l, hh);
    float eh = __expf(l + hh + g_Qb[row * NHD + h]);

    red_add1(&g_D[row * NHD + h], eh);

    const uint4* wvp = reinterpret_cast<const uint4*>(g_Wv) + (size_t)e * 2;
    u64 wv2[8], v2[8];
    cvt8(wvp[0], wv2); cvt8(wvp[1], wv2 + 4);
    cvt8(kv[8 + h * 2], v2); cvt8(kv[8 + h * 2 + 1], v2 + 4);

    u64 eh2 = pack2(eh, eh);
    float* Up = g_U + (size_t)row * HCH + h * PH;
#pragma unroll
    for (int q = 0; q < 4; q++) {
        u64 p0 = fmul2(fmul2(wv2[2*q],   v2[2*q]),   eh2);
        u64 p1 = fmul2(fmul2(wv2[2*q+1], v2[2*q+1]), eh2);
        float a, b, c, d;
        unpack2(p0, a, b); unpack2(p1, c, d);
        red_add4(Up + 4 * q, a, b, c, d);
    }
}

// ---------------------------------------------------------------------------
// Kernel 3 (fused epilogue). Weight rows loaded in TWO 8-float4 passes with
// per-node accumulators held across passes -> ~half the registers of R9.
// ---------------------------------------------------------------------------
#define ANB 48
#define NR  (ANB / 4)      // nodes per thread-group = 12
__global__ __launch_bounds__(256)
void k_out(const float* __restrict__ x,
           const float* __restrict__ wvlw, const float* __restrict__ wvlb,
           const float* __restrict__ cenw, const float* __restrict__ cenb,
           const float* __restrict__ outw, const float* __restrict__ outb,
           float* __restrict__ y) {
    __shared__ __align__(16) float s_x[ANB * 68];
    __shared__ __align__(16) float s_u[ANB * 68];
    __shared__ __align__(16) float s_t[ANB * 68];
    __shared__ __align__(16) float s_wvl[256];
    __shared__ float s_d[ANB * NHD];

    int tid = threadIdx.x;
    int o = tid & 63, g = tid >> 6;
    int n0 = blockIdx.x * ANB;

    for (int f = tid; f < ANB * 16; f += 256) {
        int r = f >> 4, c = f & 15;
        int n = n0 + r;
        float4 vx = make_float4(0.f, 0.f, 0.f, 0.f), vu = vx;
        if (n < NN) {
            vx = reinterpret_cast<const float4*>(x)[(size_t)n * 16 + c];
            vu = reinterpret_cast<const float4*>(g_U)[(size_t)n * 16 + c];
        }
        *(float4*)&s_x[r * 68 + c * 4] = vx;
        *(float4*)&s_u[r * 68 + c * 4] = vu;
    }
    if (tid < ANB * NHD) {
        int r = tid >> 2, hh = tid & 3;
        int n = n0 + r;
        s_d[tid] = (n < NN) ? g_D[n * NHD + hh] : 1.f;
    }
    if (tid < 256) s_wvl[tid] = wvlw[tid];

    int h = o >> 4, oo = o & 15;
    float cb = cenb[o], ob = outb[o], vb = wvlb[oo];
    __syncthreads();

    float acc[NR];
    const float4* wvl4 = (const float4*)s_wvl;

    // aggr + cen bias into accumulators
#pragma unroll
    for (int ri = 0; ri < NR; ri++) {
        int r = g + 4 * ri;
        const float* ur = &s_u[r * 68 + h * 16];
        float a = 0.f;
#pragma unroll
        for (int q = 0; q < 4; q++) {
            float4 wl = wvl4[oo * 4 + q];
            float4 u4 = *(const float4*)&ur[4 * q];
            a += wl.x * u4.x + wl.y * u4.y + wl.z * u4.z + wl.w * u4.w;
        }
        float d = s_d[r * NHD + h];
        acc[ri] = cb + ((d > 0.f) ? (a / d + vb) : 0.f);
    }

    // cen @ x in two weight-half passes (8 float4 live at a time)
    {
        float4 w[8];
#pragma unroll
        for (int half = 0; half < 2; half++) {
#pragma unroll
            for (int q = 0; q < 8; q++)
                w[q] = reinterpret_cast<const float4*>(cenw)[o * 16 + half * 8 + q];
#pragma unroll
            for (int ri = 0; ri < NR; ri++) {
                const float* xr = &s_x[(g + 4 * ri) * 68 + half * 32];
                float a = acc[ri];
#pragma unroll
                for (int q = 0; q < 8; q++) {
                    float4 x4 = *(const float4*)&xr[4 * q];
                    a += w[q].x * x4.x + w[q].y * x4.y + w[q].z * x4.z + w[q].w * x4.w;
                }
                acc[ri] = a;
            }
        }
    }
#pragma unroll
    for (int ri = 0; ri < NR; ri++)
        s_t[(g + 4 * ri) * 68 + o] = ssp(acc[ri]);
    __syncthreads();

    // out @ t in two weight-half passes
#pragma unroll
    for (int ri = 0; ri < NR; ri++) acc[ri] = ob;
    {
        float4 w[8];
#pragma unroll
        for (int half = 0; half < 2; half++) {
#pragma unroll
            for (int q = 0; q < 8; q++)
                w[q] = reinterpret_cast<const float4*>(outw)[o * 16 + half * 8 + q];
#pragma unroll
            for (int ri = 0; ri < NR; ri++) {
                const float* tr = &s_t[(g + 4 * ri) * 68 + half * 32];
                float a = acc[ri];
#pragma unroll
                for (int q = 0; q < 8; q++) {
                    float4 t4 = *(const float4*)&tr[4 * q];
                    a += w[q].x * t4.x + w[q].y * t4.y + w[q].z * t4.z + w[q].w * t4.w;
                }
                acc[ri] = a;
            }
        }
    }
#pragma unroll
    for (int ri = 0; ri < NR; ri++) {
        int n = n0 + g + 4 * ri;
        if (n < NN) y[(size_t)n * HCH + o] = acc[ri];
    }
}

// ---------------------------------------------------------------------------
extern "C" void kernel_launch(void* const* d_in, const int* in_sizes, int n_in,
                              void* d_out, int out_size) {
    const float* x    = (const float*)d_in[0];
    const int*   ei   = (const int*)d_in[1];
    const float* ea   = (const float*)d_in[2];
    const float* kw   = (const float*)d_in[3];
    const float* qw   = (const float*)d_in[4];
    const float* vw   = (const float*)d_in[5];
    const float* wk1  = (const float*)d_in[6];
    const float* bk1  = (const float*)d_in[7];
    const float* wk2  = (const float*)d_in[8];
    const float* bk2  = (const float*)d_in[9];
    const float* wklw = (const float*)d_in[10];
    const float* wklb = (const float*)d_in[11];
    const float* wv1  = (const float*)d_in[12];
    const float* bv1  = (const float*)d_in[13];
    const float* wv2  = (const float*)d_in[14];
    const float* bv2  = (const float*)d_in[15];
    const float* wvlw = (const float*)d_in[16];
    const float* wvlb = (const float*)d_in[17];
    const float* cenw = (const float*)d_in[18];
    const float* cenb = (const float*)d_in[19];
    const float* outw = (const float*)d_in[20];
    const float* outb = (const float*)d_in[21];
    float* out = (float*)d_out;

    k_detect<<<1, 256>>>(ei);
    k_nodes<<<(NN * NHD + 255) / 256, 256>>>(x, kw, qw, vw, wklw, wklb);
    k_mlp<<<EE / MNB, MNB>>>(ea, wk1, bk1, wk2, bk2, wv1, bv1, wv2, bv2);
    k_attn<<<(EE * NHD) / 256, 256>>>(ei);
    k_out<<<(NN + ANB - 1) / ANB, 256>>>(x, wvlw, wvlb, cenw, cenb,
                                         outw, outb, out);
}

// round 12
// speedup vs baseline: 2.0969x; 1.2070x over previous
#include <cuda_runtime.h>
#include <cuda_fp16.h>

#define NN 50000
#define EE 800000
#define HCH 64
#define ECH 32
#define NHD 4
#define PH 16

typedef unsigned long long u64;
typedef unsigned int u32;

// Scratch (device globals). Records laid out for gather coalescing:
//  g_KV[n]  : [K h0..h3 | V h0..h3]  = 256B (fp16)
//  g_Qth[n] : [Qt h0..h3]            = 128B (fp16)
//  g_Wk/g_Wv: per-edge MLP outputs   = 32B each (fp16)
__device__ __align__(16) __half g_KV [NN * 128];
__device__ __align__(16) __half g_Qth[NN * 64];
__device__ __align__(16) float  g_Qb[NN * NHD];
__device__ __align__(16) __half g_Wk[(size_t)EE * 16];
__device__ __align__(16) __half g_Wv[(size_t)EE * 16];
__device__ __align__(16) float  g_U [NN * HCH];
__device__ __align__(16) float  g_D [NN * NHD];
__device__ int g_idx64;

// fast shifted-softplus: max(v,0) + log(0.5*exp(-|v|) + 0.5)
__device__ __forceinline__ float ssp(float v) {
    return fmaxf(v, 0.f) + __logf(fmaf(0.5f, __expf(-fabsf(v)), 0.5f));
}

// ---- packed f32x2 helpers (sm_103a) ----
__device__ __forceinline__ u64 pack2(float lo, float hi) {
    u64 d; asm("mov.b64 %0, {%1, %2};" : "=l"(d) : "f"(lo), "f"(hi)); return d;
}
__device__ __forceinline__ void unpack2(u64 a, float& lo, float& hi) {
    asm("mov.b64 {%0, %1}, %2;" : "=f"(lo), "=f"(hi) : "l"(a));
}
__device__ __forceinline__ u64 ffma2(u64 a, u64 b, u64 c) {
    u64 d; asm("fma.rn.f32x2 %0, %1, %2, %3;" : "=l"(d) : "l"(a), "l"(b), "l"(c)); return d;
}
__device__ __forceinline__ u64 fmul2(u64 a, u64 b) {
    u64 d; asm("mul.rn.f32x2 %0, %1, %2;" : "=l"(d) : "l"(a), "l"(b)); return d;
}

// uint4 (8 halves) -> 4 packed f32x2
__device__ __forceinline__ void cvt8(uint4 r, u64* out) {
    const __half2* h = reinterpret_cast<const __half2*>(&r);
#pragma unroll
    for (int i = 0; i < 4; i++) {
        float2 f = __half22float2(h[i]);
        out[i] = pack2(f.x, f.y);
    }
}

__device__ __forceinline__ void ld16(const float* __restrict__ p, float* r) {
#pragma unroll
    for (int i = 0; i < 4; i++) {
        float4 v = reinterpret_cast<const float4*>(p)[i];
        r[4*i+0] = v.x; r[4*i+1] = v.y; r[4*i+2] = v.z; r[4*i+3] = v.w;
    }
}

__device__ __forceinline__ uint4 toh8(const float* r) {
    uint4 o;
    __half2* h = reinterpret_cast<__half2*>(&o);
#pragma unroll
    for (int i = 0; i < 4; i++)
        h[i] = __float22half2_rn(make_float2(r[2*i], r[2*i+1]));
    return o;
}

__device__ __forceinline__ u32 h2(float a, float b) {
    __half2 h = __floats2half2_rn(a, b);
    return *reinterpret_cast<u32*>(&h);
}

__device__ __forceinline__ void red_add4(float* p, float a, float b, float c, float d) {
    asm volatile("red.global.add.v4.f32 [%0], {%1,%2,%3,%4};"
                 :: "l"(__cvta_generic_to_global(p)),
                    "f"(a), "f"(b), "f"(c), "f"(d) : "memory");
}
__device__ __forceinline__ void red_add1(float* p, float a) {
    asm volatile("red.global.add.f32 [%0], %1;"
                 :: "l"(__cvta_generic_to_global(p)), "f"(a) : "memory");
}

// m16n8k16 f16 MMA, f32 accumulate in place.
__device__ __forceinline__ void mma16816(float d[4], const u32 a[4], const u32 b[2]) {
    asm volatile("mma.sync.aligned.m16n8k16.row.col.f32.f16.f16.f32 "
        "{%0,%1,%2,%3},{%4,%5,%6,%7},{%8,%9},{%0,%1,%2,%3};"
        : "+f"(d[0]), "+f"(d[1]), "+f"(d[2]), "+f"(d[3])
        : "r"(a[0]), "r"(a[1]), "r"(a[2]), "r"(a[3]), "r"(b[0]), "r"(b[1]));
}

// ---------------------------------------------------------------------------
__global__ void k_detect(const int* __restrict__ ei_w) {
    int bad = __syncthreads_or(ei_w[2 * threadIdx.x + 1] != 0);
    if (threadIdx.x == 0) g_idx64 = bad ? 0 : 1;
}

// ---------------------------------------------------------------------------
// Kernel 1: node precompute (K,V,Qt fp16 records; qb f32; zero accumulators)
// ---------------------------------------------------------------------------
__global__ __launch_bounds__(256)
void k_nodes(const float* __restrict__ x,
             const float* __restrict__ kw, const float* __restrict__ qw,
             const float* __restrict__ vw,
             const float* __restrict__ wklw, const float* __restrict__ wklb) {
    __shared__ __align__(16) float s_k[1024], s_q[1024], s_v[1024], s_l[256], s_lb[16];
    for (int i = threadIdx.x; i < 1024; i += 256) {
        s_k[i] = kw[i]; s_q[i] = qw[i]; s_v[i] = vw[i];
    }
    if (threadIdx.x < 256) s_l[threadIdx.x] = wklw[threadIdx.x];
    if (threadIdx.x < 16)  s_lb[threadIdx.x] = wklb[threadIdx.x];
    __syncthreads();

    int t = blockIdx.x * 256 + threadIdx.x;
    if (t >= NN * NHD) return;
    int n = t >> 2, h = t & 3;

    float xv[PH];
    ld16(x + (size_t)n * HCH + h * PH, xv);

    const float4* wkh = (const float4*)(s_k + h * 256);
    const float4* wqh = (const float4*)(s_q + h * 256);
    const float4* wvh = (const float4*)(s_v + h * 256);

    float kk[PH], vv[PH], qq[PH];
#pragma unroll
    for (int o = 0; o < PH; o++) {
        float a = 0.f, b = 0.f, c = 0.f;
#pragma unroll
        for (int q = 0; q < 4; q++) {
            float4 wk = wkh[o * 4 + q];
            float4 wq = wqh[o * 4 + q];
            float4 wv = wvh[o * 4 + q];
            a += xv[4*q]*wk.x + xv[4*q+1]*wk.y + xv[4*q+2]*wk.z + xv[4*q+3]*wk.w;
            b += xv[4*q]*wq.x + xv[4*q+1]*wq.y + xv[4*q+2]*wq.z + xv[4*q+3]*wq.w;
            c += xv[4*q]*wv.x + xv[4*q+1]*wv.y + xv[4*q+2]*wv.z + xv[4*q+3]*wv.w;
        }
        kk[o] = a; qq[o] = b; vv[o] = c;
    }

    float qt[PH];
#pragma unroll
    for (int i = 0; i < PH; i++) {
        float a = 0.f;
#pragma unroll
        for (int o = 0; o < PH; o++) a += qq[o] * s_l[o * PH + i];
        qt[i] = a;
    }
    float qb = 0.f;
#pragma unroll
    for (int o = 0; o < PH; o++) qb += qq[o] * s_lb[o];

    uint4* kvb = reinterpret_cast<uint4*>(g_KV + (size_t)n * 128);
    kvb[h * 2 + 0] = toh8(kk);
    kvb[h * 2 + 1] = toh8(kk + 8);
    kvb[8 + h * 2 + 0] = toh8(vv);
    kvb[8 + h * 2 + 1] = toh8(vv + 8);
    uint4* qtb = reinterpret_cast<uint4*>(g_Qth + (size_t)n * 64);
    qtb[h * 2 + 0] = toh8(qt);
    qtb[h * 2 + 1] = toh8(qt + 8);
    g_Qb[t] = qb;

    float4 z = make_float4(0.f, 0.f, 0.f, 0.f);
#pragma unroll
    for (int i = 0; i < 4; i++)
        reinterpret_cast<float4*>(g_U + (size_t)t * PH)[i] = z;
    g_D[t] = 0.f;
}

// ---------------------------------------------------------------------------
// Kernel 2a (tensor-core): per-edge MLPs as two chained GEMMs via
// mma.sync.m16n8k16 (f16 in, f32 accum). Both nets fused into one 32-wide
// combined weight; layer2 is block-diagonal. The m16n8 C-fragment layout maps
// exactly onto the next layer's A-fragment (row g/g+8, cols t*2..), so the
// ssp activation chains in registers with no shuffles.
// ---------------------------------------------------------------------------
#define MLP_GRID 1480
__global__ __launch_bounds__(256)
void k_mlp(const float* __restrict__ ea,
           const float* __restrict__ wk1, const float* __restrict__ bk1,
           const float* __restrict__ wk2, const float* __restrict__ bk2,
           const float* __restrict__ wv1, const float* __restrict__ bv1,
           const float* __restrict__ wv2, const float* __restrict__ bv2) {
    __shared__ __align__(16) float s_w1[32 * 33];   // transposed combined [in][out]
    __shared__ __align__(16) float s_w2[32 * 33];
    __shared__ float s_b1[32], s_b2[32];
    __shared__ __align__(16) __half s_a[128 * 36];  // 128 edges x 32 attrs (fp16, padded)

    int tid = threadIdx.x;
    for (int idx = tid; idx < 1024; idx += 256) {
        int j = idx >> 5, i = idx & 31;             // j = out, i = in
        float w1 = (j < 16) ? wk1[j * 32 + i] : wv1[(j - 16) * 32 + i];
        float w2 = 0.f;
        if (j < 16 && i < 16)   w2 = wk2[j * 16 + i];
        if (j >= 16 && i >= 16) w2 = wv2[(j - 16) * 16 + (i - 16)];
        s_w1[i * 33 + j] = w1;
        s_w2[i * 33 + j] = w2;
    }
    if (tid < 32) {
        s_b1[tid] = (tid < 16) ? bk1[tid] : bv1[tid - 16];
        s_b2[tid] = (tid < 16) ? bk2[tid] : bv2[tid - 16];
    }
    __syncthreads();

    int lane = tid & 31;
    int g = lane >> 2, t = lane & 3;
    int warp = tid >> 5;

    // Per-thread B fragments (built once, amortized over the grid-stride loop)
    u32 B1[4][2][2], B2[4][2][2];
    float bia1[4][2], bia2[4][2];
#pragma unroll
    for (int nt = 0; nt < 4; nt++) {
        int j = nt * 8 + g;
#pragma unroll
        for (int kk = 0; kk < 2; kk++) {
#pragma unroll
            for (int r = 0; r < 2; r++) {
                int i0 = kk * 16 + r * 8 + t * 2;
                B1[nt][kk][r] = h2(s_w1[i0 * 33 + j], s_w1[(i0 + 1) * 33 + j]);
                B2[nt][kk][r] = h2(s_w2[i0 * 33 + j], s_w2[(i0 + 1) * 33 + j]);
            }
        }
        bia1[nt][0] = s_b1[nt * 8 + t * 2]; bia1[nt][1] = s_b1[nt * 8 + t * 2 + 1];
        bia2[nt][0] = s_b2[nt * 8 + t * 2]; bia2[nt][1] = s_b2[nt * 8 + t * 2 + 1];
    }

    for (long long base = (long long)blockIdx.x * 128; base < EE;
         base += (long long)gridDim.x * 128) {
        __syncthreads();   // previous iteration's reads of s_a must complete
        // stage 128 edges -> fp16 shared (coalesced float4 loads)
        const float4* ea4 = reinterpret_cast<const float4*>(ea) + base * 8;
#pragma unroll
        for (int kq = 0; kq < 4; kq++) {
            int f = tid + kq * 256;                 // [0,1024): r = f>>3, c4 = f&7
            float4 v = ea4[f];
            int r = f >> 3, c4 = f & 7;
            *(u32*)&s_a[r * 36 + c4 * 4 + 0] = h2(v.x, v.y);
            *(u32*)&s_a[r * 36 + c4 * 4 + 2] = h2(v.z, v.w);
        }
        __syncthreads();

        const __half* arow0 = &s_a[(warp * 16 + g) * 36];
        const __half* arow1 = &s_a[(warp * 16 + g + 8) * 36];
        u32 A[2][4];
#pragma unroll
        for (int kk = 0; kk < 2; kk++) {
            A[kk][0] = *(const u32*)&arow0[kk * 16 + t * 2];
            A[kk][1] = *(const u32*)&arow1[kk * 16 + t * 2];
            A[kk][2] = *(const u32*)&arow0[kk * 16 + t * 2 + 8];
            A[kk][3] = *(const u32*)&arow1[kk * 16 + t * 2 + 8];
        }

        float C[4][4];
#pragma unroll
        for (int nt = 0; nt < 4; nt++) {
            C[nt][0] = C[nt][1] = C[nt][2] = C[nt][3] = 0.f;
            mma16816(C[nt], A[0], B1[nt][0]);
            mma16816(C[nt], A[1], B1[nt][1]);
        }

        // ssp activation; repack C-fragments directly as layer2 A-fragments
        u32 A2[2][4];
#pragma unroll
        for (int kk = 0; kk < 2; kk++) {
            int na = 2 * kk, nb = 2 * kk + 1;
            A2[kk][0] = h2(ssp(C[na][0] + bia1[na][0]), ssp(C[na][1] + bia1[na][1]));
            A2[kk][1] = h2(ssp(C[na][2] + bia1[na][0]), ssp(C[na][3] + bia1[na][1]));
            A2[kk][2] = h2(ssp(C[nb][0] + bia1[nb][0]), ssp(C[nb][1] + bia1[nb][1]));
            A2[kk][3] = h2(ssp(C[nb][2] + bia1[nb][0]), ssp(C[nb][3] + bia1[nb][1]));
        }

        float D[4][4];
#pragma unroll
        for (int nt = 0; nt < 4; nt++) {
            D[nt][0] = D[nt][1] = D[nt][2] = D[nt][3] = 0.f;
            mma16816(D[nt], A2[0], B2[nt][0]);
            mma16816(D[nt], A2[1], B2[nt][1]);
        }

        // store: cols 0..15 -> W_k, 16..31 -> W_v (fp16, u32 per pair)
        size_t eg  = (size_t)base + warp * 16 + g;
        size_t eg8 = eg + 8;
#pragma unroll
        for (int nt = 0; nt < 4; nt++) {
            int col = nt * 8 + t * 2;
            u32 lo = h2(D[nt][0] + bia2[nt][0], D[nt][1] + bia2[nt][1]);
            u32 hi = h2(D[nt][2] + bia2[nt][0], D[nt][3] + bia2[nt][1]);
            __half* d0 = (col < 16) ? (g_Wk + eg  * 16 + col) : (g_Wv + eg  * 16 + col - 16);
            __half* d8 = (col < 16) ? (g_Wk + eg8 * 16 + col) : (g_Wv + eg8 * 16 + col - 16);
            *(u32*)d0 = lo;
            *(u32*)d8 = hi;
        }
    }
}

// ---------------------------------------------------------------------------
// Kernel 2b: attention gather pass, thread per (edge, head). (unchanged)
// ---------------------------------------------------------------------------
__global__ __launch_bounds__(256)
void k_attn(const int* __restrict__ ei) {
    int idx = blockIdx.x * 256 + threadIdx.x;
    int e = idx >> 2, h = idx & 3;

    int row, col;
    if (g_idx64) {
        const long long* p = (const long long*)ei;
        row = (int)p[e];
        col = (int)p[(size_t)EE + e];
    } else {
        row = ei[e];
        col = ei[EE + e];
    }

    const uint4* kv  = reinterpret_cast<const uint4*>(g_KV)  + (size_t)col * 16;
    const uint4* qt  = reinterpret_cast<const uint4*>(g_Qth) + (size_t)row * 8;
    const uint4* wkp = reinterpret_cast<const uint4*>(g_Wk)  + (size_t)e * 2;

    u64 wk2[8], k2[8], q2[8];
    cvt8(wkp[0], wk2); cvt8(wkp[1], wk2 + 4);
    cvt8(kv[h * 2], k2); cvt8(kv[h * 2 + 1], k2 + 4);
    cvt8(qt[h * 2], q2); cvt8(qt[h * 2 + 1], q2 + 4);

    u64 acc = 0ull;
#pragma unroll
    for (int i = 0; i < 8; i++)
        acc = ffma2(wk2[i], fmul2(k2[i], q2[i]), acc);
    float l, hh;
    unpack2(acc, l, hh);
    float eh = __expf(l + hh + g_Qb[row * NHD + h]);

    red_add1(&g_D[row * NHD + h], eh);

    const uint4* wvp = reinterpret_cast<const uint4*>(g_Wv) + (size_t)e * 2;
    u64 wv2[8], v2[8];
    cvt8(wvp[0], wv2); cvt8(wvp[1], wv2 + 4);
    cvt8(kv[8 + h * 2], v2); cvt8(kv[8 + h * 2 + 1], v2 + 4);

    u64 eh2 = pack2(eh, eh);
    float* Up = g_U + (size_t)row * HCH + h * PH;
#pragma unroll
    for (int q = 0; q < 4; q++) {
        u64 p0 = fmul2(fmul2(wv2[2*q],   v2[2*q]),   eh2);
        u64 p1 = fmul2(fmul2(wv2[2*q+1], v2[2*q+1]), eh2);
        float a, b, c, d;
        unpack2(p0, a, b); unpack2(p1, c, d);
        red_add4(Up + 4 * q, a, b, c, d);
    }
}

// ---------------------------------------------------------------------------
// Kernel 3 (fused epilogue): unchanged from R11.
// ---------------------------------------------------------------------------
#define ANB 48
#define NR  (ANB / 4)
__global__ __launch_bounds__(256)
void k_out(const float* __restrict__ x,
           const float* __restrict__ wvlw, const float* __restrict__ wvlb,
           const float* __restrict__ cenw, const float* __restrict__ cenb,
           const float* __restrict__ outw, const float* __restrict__ outb,
           float* __restrict__ y) {
    __shared__ __align__(16) float s_x[ANB * 68];
    __shared__ __align__(16) float s_u[ANB * 68];
    __shared__ __align__(16) float s_t[ANB * 68];
    __shared__ __align__(16) float s_wvl[256];
    __shared__ float s_d[ANB * NHD];

    int tid = threadIdx.x;
    int o = tid & 63, g = tid >> 6;
    int n0 = blockIdx.x * ANB;

    for (int f = tid; f < ANB * 16; f += 256) {
        int r = f >> 4, c = f & 15;
        int n = n0 + r;
        float4 vx = make_float4(0.f, 0.f, 0.f, 0.f), vu = vx;
        if (n < NN) {
            vx = reinterpret_cast<const float4*>(x)[(size_t)n * 16 + c];
            vu = reinterpret_cast<const float4*>(g_U)[(size_t)n * 16 + c];
        }
        *(float4*)&s_x[r * 68 + c * 4] = vx;
        *(float4*)&s_u[r * 68 + c * 4] = vu;
    }
    if (tid < ANB * NHD) {
        int r = tid >> 2, hh = tid & 3;
        int n = n0 + r;
        s_d[tid] = (n < NN) ? g_D[n * NHD + hh] : 1.f;
    }
    if (tid < 256) s_wvl[tid] = wvlw[tid];

    int h = o >> 4, oo = o & 15;
    float cb = cenb[o], ob = outb[o], vb = wvlb[oo];
    __syncthreads();

    float acc[NR];
    const float4* wvl4 = (const float4*)s_wvl;

#pragma unroll
    for (int ri = 0; ri < NR; ri++) {
        int r = g + 4 * ri;
        const float* ur = &s_u[r * 68 + h * 16];
        float a = 0.f;
#pragma unroll
        for (int q = 0; q < 4; q++) {
            float4 wl = wvl4[oo * 4 + q];
            float4 u4 = *(const float4*)&ur[4 * q];
            a += wl.x * u4.x + wl.y * u4.y + wl.z * u4.z + wl.w * u4.w;
        }
        float d = s_d[r * NHD + h];
        acc[ri] = cb + ((d > 0.f) ? (a / d + vb) : 0.f);
    }

    {
        float4 w[8];
#pragma unroll
        for (int half = 0; half < 2; half++) {
#pragma unroll
            for (int q = 0; q < 8; q++)
                w[q] = reinterpret_cast<const float4*>(cenw)[o * 16 + half * 8 + q];
#pragma unroll
            for (int ri = 0; ri < NR; ri++) {
                const float* xr = &s_x[(g + 4 * ri) * 68 + half * 32];
                float a = acc[ri];
#pragma unroll
                for (int q = 0; q < 8; q++) {
                    float4 x4 = *(const float4*)&xr[4 * q];
                    a += w[q].x * x4.x + w[q].y * x4.y + w[q].z * x4.z + w[q].w * x4.w;
                }
                acc[ri] = a;
            }
        }
    }
#pragma unroll
    for (int ri = 0; ri < NR; ri++)
        s_t[(g + 4 * ri) * 68 + o] = ssp(acc[ri]);
    __syncthreads();

#pragma unroll
    for (int ri = 0; ri < NR; ri++) acc[ri] = ob;
    {
        float4 w[8];
#pragma unroll
        for (int half = 0; half < 2; half++) {
#pragma unroll
            for (int q = 0; q < 8; q++)
                w[q] = reinterpret_cast<const float4*>(outw)[o * 16 + half * 8 + q];
#pragma unroll
            for (int ri = 0; ri < NR; ri++) {
                const float* tr = &s_t[(g + 4 * ri) * 68 + half * 32];
                float a = acc[ri];
#pragma unroll
                for (int q = 0; q < 8; q++) {
                    float4 t4 = *(const float4*)&tr[4 * q];
                    a += w[q].x * t4.x + w[q].y * t4.y + w[q].z * t4.z + w[q].w * t4.w;
                }
                acc[ri] = a;
            }
        }
    }
#pragma unroll
    for (int ri = 0; ri < NR; ri++) {
        int n = n0 + g + 4 * ri;
        if (n < NN) y[(size_t)n * HCH + o] = acc[ri];
    }
}

// ---------------------------------------------------------------------------
extern "C" void kernel_launch(void* const* d_in, const int* in_sizes, int n_in,
                              void* d_out, int out_size) {
    const float* x    = (const float*)d_in[0];
    const int*   ei   = (const int*)d_in[1];
    const float* ea   = (const float*)d_in[2];
    const float* kw   = (const float*)d_in[3];
    const float* qw   = (const float*)d_in[4];
    const float* vw   = (const float*)d_in[5];
    const float* wk1  = (const float*)d_in[6];
    const float* bk1  = (const float*)d_in[7];
    const float* wk2  = (const float*)d_in[8];
    const float* bk2  = (const float*)d_in[9];
    const float* wklw = (const float*)d_in[10];
    const float* wklb = (const float*)d_in[11];
    const float* wv1  = (const float*)d_in[12];
    const float* bv1  = (const float*)d_in[13];
    const float* wv2  = (const float*)d_in[14];
    const float* bv2  = (const float*)d_in[15];
    const float* wvlw = (const float*)d_in[16];
    const float* wvlb = (const float*)d_in[17];
    const float* cenw = (const float*)d_in[18];
    const float* cenb = (const float*)d_in[19];
    const float* outw = (const float*)d_in[20];
    const float* outb = (const float*)d_in[21];
    float* out = (float*)d_out;

    k_detect<<<1, 256>>>(ei);
    k_nodes<<<(NN * NHD + 255) / 256, 256>>>(x, kw, qw, vw, wklw, wklb);
    k_mlp<<<MLP_GRID, 256>>>(ea, wk1, bk1, wk2, bk2, wv1, bv1, wv2, bv2);
    k_attn<<<(EE * NHD) / 256, 256>>>(ei);
    k_out<<<(NN + ANB - 1) / ANB, 256>>>(x, wvlw, wvlb, cenw, cenb,
                                         outw, outb, out);
}

// round 13
// speedup vs baseline: 2.3155x; 1.1043x over previous
#include <cuda_runtime.h>
#include <cuda_fp16.h>

#define NN 50000
#define EE 800000
#define HCH 64
#define ECH 32
#define NHD 4
#define PH 16

typedef unsigned long long u64;
typedef unsigned int u32;

// Scratch (device globals).
__device__ __align__(16) __half g_KV [NN * 128];
__device__ __align__(16) __half g_Qth[NN * 64];
__device__ __align__(16) float  g_Qb[NN * NHD];
__device__ __align__(16) __half g_Wk[(size_t)EE * 16];
__device__ __align__(16) __half g_Wv[(size_t)EE * 16];
__device__ __align__(16) float  g_U [NN * HCH];
__device__ __align__(16) float  g_D [NN * NHD];
__device__ int g_idx64;

__device__ __forceinline__ float ssp(float v) {
    return fmaxf(v, 0.f) + __logf(fmaf(0.5f, __expf(-fabsf(v)), 0.5f));
}

// ---- packed f32x2 helpers ----
__device__ __forceinline__ u64 pack2(float lo, float hi) {
    u64 d; asm("mov.b64 %0, {%1, %2};" : "=l"(d) : "f"(lo), "f"(hi)); return d;
}
__device__ __forceinline__ void unpack2(u64 a, float& lo, float& hi) {
    asm("mov.b64 {%0, %1}, %2;" : "=f"(lo), "=f"(hi) : "l"(a));
}
__device__ __forceinline__ u64 ffma2(u64 a, u64 b, u64 c) {
    u64 d; asm("fma.rn.f32x2 %0, %1, %2, %3;" : "=l"(d) : "l"(a), "l"(b), "l"(c)); return d;
}
__device__ __forceinline__ u64 fmul2(u64 a, u64 b) {
    u64 d; asm("mul.rn.f32x2 %0, %1, %2;" : "=l"(d) : "l"(a), "l"(b)); return d;
}
__device__ __forceinline__ void cvt8(uint4 r, u64* out) {
    const __half2* h = reinterpret_cast<const __half2*>(&r);
#pragma unroll
    for (int i = 0; i < 4; i++) {
        float2 f = __half22float2(h[i]);
        out[i] = pack2(f.x, f.y);
    }
}
__device__ __forceinline__ void ld16(const float* __restrict__ p, float* r) {
#pragma unroll
    for (int i = 0; i < 4; i++) {
        float4 v = reinterpret_cast<const float4*>(p)[i];
        r[4*i+0] = v.x; r[4*i+1] = v.y; r[4*i+2] = v.z; r[4*i+3] = v.w;
    }
}
__device__ __forceinline__ uint4 toh8(const float* r) {
    uint4 o;
    __half2* h = reinterpret_cast<__half2*>(&o);
#pragma unroll
    for (int i = 0; i < 4; i++)
        h[i] = __float22half2_rn(make_float2(r[2*i], r[2*i+1]));
    return o;
}
__device__ __forceinline__ u32 h2(float a, float b) {
    __half2 h = __floats2half2_rn(a, b);
    return *reinterpret_cast<u32*>(&h);
}
__device__ __forceinline__ void red_add4(float* p, float a, float b, float c, float d) {
    asm volatile("red.global.add.v4.f32 [%0], {%1,%2,%3,%4};"
                 :: "l"(__cvta_generic_to_global(p)),
                    "f"(a), "f"(b), "f"(c), "f"(d) : "memory");
}
__device__ __forceinline__ void red_add1(float* p, float a) {
    asm volatile("red.global.add.f32 [%0], %1;"
                 :: "l"(__cvta_generic_to_global(p)), "f"(a) : "memory");
}
__device__ __forceinline__ void mma16816(float d[4], const u32 a[4], const u32 b[2]) {
    asm volatile("mma.sync.aligned.m16n8k16.row.col.f32.f16.f16.f32 "
        "{%0,%1,%2,%3},{%4,%5,%6,%7},{%8,%9},{%0,%1,%2,%3};"
        : "+f"(d[0]), "+f"(d[1]), "+f"(d[2]), "+f"(d[3])
        : "r"(a[0]), "r"(a[1]), "r"(a[2]), "r"(a[3]), "r"(b[0]), "r"(b[1]));
}

// ---------------------------------------------------------------------------
__global__ void k_detect(const int* __restrict__ ei_w) {
    int bad = __syncthreads_or(ei_w[2 * threadIdx.x + 1] != 0);
    if (threadIdx.x == 0) g_idx64 = bad ? 0 : 1;
}

// ---------------------------------------------------------------------------
// Kernel 1: node precompute (unchanged from R12)
// ---------------------------------------------------------------------------
__global__ __launch_bounds__(256)
void k_nodes(const float* __restrict__ x,
             const float* __restrict__ kw, const float* __restrict__ qw,
             const float* __restrict__ vw,
             const float* __restrict__ wklw, const float* __restrict__ wklb) {
    __shared__ __align__(16) float s_k[1024], s_q[1024], s_v[1024], s_l[256], s_lb[16];
    for (int i = threadIdx.x; i < 1024; i += 256) {
        s_k[i] = kw[i]; s_q[i] = qw[i]; s_v[i] = vw[i];
    }
    if (threadIdx.x < 256) s_l[threadIdx.x] = wklw[threadIdx.x];
    if (threadIdx.x < 16)  s_lb[threadIdx.x] = wklb[threadIdx.x];
    __syncthreads();

    int t = blockIdx.x * 256 + threadIdx.x;
    if (t >= NN * NHD) return;
    int n = t >> 2, h = t & 3;

    float xv[PH];
    ld16(x + (size_t)n * HCH + h * PH, xv);

    const float4* wkh = (const float4*)(s_k + h * 256);
    const float4* wqh = (const float4*)(s_q + h * 256);
    const float4* wvh = (const float4*)(s_v + h * 256);

    float kk[PH], vv[PH], qq[PH];
#pragma unroll
    for (int o = 0; o < PH; o++) {
        float a = 0.f, b = 0.f, c = 0.f;
#pragma unroll
        for (int q = 0; q < 4; q++) {
            float4 wk = wkh[o * 4 + q];
            float4 wq = wqh[o * 4 + q];
            float4 wv = wvh[o * 4 + q];
            a += xv[4*q]*wk.x + xv[4*q+1]*wk.y + xv[4*q+2]*wk.z + xv[4*q+3]*wk.w;
            b += xv[4*q]*wq.x + xv[4*q+1]*wq.y + xv[4*q+2]*wq.z + xv[4*q+3]*wq.w;
            c += xv[4*q]*wv.x + xv[4*q+1]*wv.y + xv[4*q+2]*wv.z + xv[4*q+3]*wv.w;
        }
        kk[o] = a; qq[o] = b; vv[o] = c;
    }

    float qt[PH];
#pragma unroll
    for (int i = 0; i < PH; i++) {
        float a = 0.f;
#pragma unroll
        for (int o = 0; o < PH; o++) a += qq[o] * s_l[o * PH + i];
        qt[i] = a;
    }
    float qb = 0.f;
#pragma unroll
    for (int o = 0; o < PH; o++) qb += qq[o] * s_lb[o];

    uint4* kvb = reinterpret_cast<uint4*>(g_KV + (size_t)n * 128);
    kvb[h * 2 + 0] = toh8(kk);
    kvb[h * 2 + 1] = toh8(kk + 8);
    kvb[8 + h * 2 + 0] = toh8(vv);
    kvb[8 + h * 2 + 1] = toh8(vv + 8);
    uint4* qtb = reinterpret_cast<uint4*>(g_Qth + (size_t)n * 64);
    qtb[h * 2 + 0] = toh8(qt);
    qtb[h * 2 + 1] = toh8(qt + 8);
    g_Qb[t] = qb;

    float4 z = make_float4(0.f, 0.f, 0.f, 0.f);
#pragma unroll
    for (int i = 0; i < 4; i++)
        reinterpret_cast<float4*>(g_U + (size_t)t * PH)[i] = z;
    g_D[t] = 0.f;
}

// ---------------------------------------------------------------------------
// Kernel 2a (tensor-core MLP): unchanged from R12.
// ---------------------------------------------------------------------------
#define MLP_GRID 1480
__global__ __launch_bounds__(256)
void k_mlp(const float* __restrict__ ea,
           const float* __restrict__ wk1, const float* __restrict__ bk1,
           const float* __restrict__ wk2, const float* __restrict__ bk2,
           const float* __restrict__ wv1, const float* __restrict__ bv1,
           const float* __restrict__ wv2, const float* __restrict__ bv2) {
    __shared__ __align__(16) float s_w1[32 * 33];
    __shared__ __align__(16) float s_w2[32 * 33];
    __shared__ float s_b1[32], s_b2[32];
    __shared__ __align__(16) __half s_a[128 * 36];

    int tid = threadIdx.x;
    for (int idx = tid; idx < 1024; idx += 256) {
        int j = idx >> 5, i = idx & 31;
        float w1 = (j < 16) ? wk1[j * 32 + i] : wv1[(j - 16) * 32 + i];
        float w2 = 0.f;
        if (j < 16 && i < 16)   w2 = wk2[j * 16 + i];
        if (j >= 16 && i >= 16) w2 = wv2[(j - 16) * 16 + (i - 16)];
        s_w1[i * 33 + j] = w1;
        s_w2[i * 33 + j] = w2;
    }
    if (tid < 32) {
        s_b1[tid] = (tid < 16) ? bk1[tid] : bv1[tid - 16];
        s_b2[tid] = (tid < 16) ? bk2[tid] : bv2[tid - 16];
    }
    __syncthreads();

    int lane = tid & 31;
    int g = lane >> 2, t = lane & 3;
    int warp = tid >> 5;

    u32 B1[4][2][2], B2[4][2][2];
    float bia1[4][2], bia2[4][2];
#pragma unroll
    for (int nt = 0; nt < 4; nt++) {
        int j = nt * 8 + g;
#pragma unroll
        for (int kk = 0; kk < 2; kk++) {
#pragma unroll
            for (int r = 0; r < 2; r++) {
                int i0 = kk * 16 + r * 8 + t * 2;
                B1[nt][kk][r] = h2(s_w1[i0 * 33 + j], s_w1[(i0 + 1) * 33 + j]);
                B2[nt][kk][r] = h2(s_w2[i0 * 33 + j], s_w2[(i0 + 1) * 33 + j]);
            }
        }
        bia1[nt][0] = s_b1[nt * 8 + t * 2]; bia1[nt][1] = s_b1[nt * 8 + t * 2 + 1];
        bia2[nt][0] = s_b2[nt * 8 + t * 2]; bia2[nt][1] = s_b2[nt * 8 + t * 2 + 1];
    }

    for (long long base = (long long)blockIdx.x * 128; base < EE;
         base += (long long)gridDim.x * 128) {
        __syncthreads();
        const float4* ea4 = reinterpret_cast<const float4*>(ea) + base * 8;
#pragma unroll
        for (int kq = 0; kq < 4; kq++) {
            int f = tid + kq * 256;
            float4 v = ea4[f];
            int r = f >> 3, c4 = f & 7;
            *(u32*)&s_a[r * 36 + c4 * 4 + 0] = h2(v.x, v.y);
            *(u32*)&s_a[r * 36 + c4 * 4 + 2] = h2(v.z, v.w);
        }
        __syncthreads();

        const __half* arow0 = &s_a[(warp * 16 + g) * 36];
        const __half* arow1 = &s_a[(warp * 16 + g + 8) * 36];
        u32 A[2][4];
#pragma unroll
        for (int kk = 0; kk < 2; kk++) {
            A[kk][0] = *(const u32*)&arow0[kk * 16 + t * 2];
            A[kk][1] = *(const u32*)&arow1[kk * 16 + t * 2];
            A[kk][2] = *(const u32*)&arow0[kk * 16 + t * 2 + 8];
            A[kk][3] = *(const u32*)&arow1[kk * 16 + t * 2 + 8];
        }

        float C[4][4];
#pragma unroll
        for (int nt = 0; nt < 4; nt++) {
            C[nt][0] = C[nt][1] = C[nt][2] = C[nt][3] = 0.f;
            mma16816(C[nt], A[0], B1[nt][0]);
            mma16816(C[nt], A[1], B1[nt][1]);
        }

        u32 A2[2][4];
#pragma unroll
        for (int kk = 0; kk < 2; kk++) {
            int na = 2 * kk, nb = 2 * kk + 1;
            A2[kk][0] = h2(ssp(C[na][0] + bia1[na][0]), ssp(C[na][1] + bia1[na][1]));
            A2[kk][1] = h2(ssp(C[na][2] + bia1[na][0]), ssp(C[na][3] + bia1[na][1]));
            A2[kk][2] = h2(ssp(C[nb][0] + bia1[nb][0]), ssp(C[nb][1] + bia1[nb][1]));
            A2[kk][3] = h2(ssp(C[nb][2] + bia1[nb][0]), ssp(C[nb][3] + bia1[nb][1]));
        }

        float D[4][4];
#pragma unroll
        for (int nt = 0; nt < 4; nt++) {
            D[nt][0] = D[nt][1] = D[nt][2] = D[nt][3] = 0.f;
            mma16816(D[nt], A2[0], B2[nt][0]);
            mma16816(D[nt], A2[1], B2[nt][1]);
        }

        size_t eg  = (size_t)base + warp * 16 + g;
        size_t eg8 = eg + 8;
#pragma unroll
        for (int nt = 0; nt < 4; nt++) {
            int col = nt * 8 + t * 2;
            u32 lo = h2(D[nt][0] + bia2[nt][0], D[nt][1] + bia2[nt][1]);
            u32 hi = h2(D[nt][2] + bia2[nt][0], D[nt][3] + bia2[nt][1]);
            __half* d0 = (col < 16) ? (g_Wk + eg  * 16 + col) : (g_Wv + eg  * 16 + col - 16);
            __half* d8 = (col < 16) ? (g_Wk + eg8 * 16 + col) : (g_Wv + eg8 * 16 + col - 16);
            *(u32*)d0 = lo;
            *(u32*)d8 = hi;
        }
    }
}

// ---------------------------------------------------------------------------
// Kernel 2b: attention gather pass (unchanged).
// ---------------------------------------------------------------------------
__global__ __launch_bounds__(256)
void k_attn(const int* __restrict__ ei) {
    int idx = blockIdx.x * 256 + threadIdx.x;
    int e = idx >> 2, h = idx & 3;

    int row, col;
    if (g_idx64) {
        const long long* p = (const long long*)ei;
        row = (int)p[e];
        col = (int)p[(size_t)EE + e];
    } else {
        row = ei[e];
        col = ei[EE + e];
    }

    const uint4* kv  = reinterpret_cast<const uint4*>(g_KV)  + (size_t)col * 16;
    const uint4* qt  = reinterpret_cast<const uint4*>(g_Qth) + (size_t)row * 8;
    const uint4* wkp = reinterpret_cast<const uint4*>(g_Wk)  + (size_t)e * 2;

    u64 wk2[8], k2[8], q2[8];
    cvt8(wkp[0], wk2); cvt8(wkp[1], wk2 + 4);
    cvt8(kv[h * 2], k2); cvt8(kv[h * 2 + 1], k2 + 4);
    cvt8(qt[h * 2], q2); cvt8(qt[h * 2 + 1], q2 + 4);

    u64 acc = 0ull;
#pragma unroll
    for (int i = 0; i < 8; i++)
        acc = ffma2(wk2[i], fmul2(k2[i], q2[i]), acc);
    float l, hh;
    unpack2(acc, l, hh);
    float eh = __expf(l + hh + g_Qb[row * NHD + h]);

    red_add1(&g_D[row * NHD + h], eh);

    const uint4* wvp = reinterpret_cast<const uint4*>(g_Wv) + (size_t)e * 2;
    u64 wv2[8], v2[8];
    cvt8(wvp[0], wv2); cvt8(wvp[1], wv2 + 4);
    cvt8(kv[8 + h * 2], v2); cvt8(kv[8 + h * 2 + 1], v2 + 4);

    u64 eh2 = pack2(eh, eh);
    float* Up = g_U + (size_t)row * HCH + h * PH;
#pragma unroll
    for (int q = 0; q < 4; q++) {
        u64 p0 = fmul2(fmul2(wv2[2*q],   v2[2*q]),   eh2);
        u64 p1 = fmul2(fmul2(wv2[2*q+1], v2[2*q+1]), eh2);
        float a, b, c, d;
        unpack2(p0, a, b); unpack2(p1, c, d);
        red_add4(Up + 4 * q, a, b, c, d);
    }
}

// ---------------------------------------------------------------------------
// Kernel 3 (tensor-core epilogue): y = outw @ ssp([x | U/D] @ Waug + cb (+vb))
// Waug = [cen^T ; wvl-blockdiag] (k=128). Layer1 C-fragments -> ssp -> shared
// t-exchange -> layer2 A-fragments (k_mlp relayout trick, n split across 2
// warps per m-tile). 64 nodes / block, 8 warps = 4 m-tiles x 2 n-halves.
// ---------------------------------------------------------------------------
__global__ __launch_bounds__(256)
void k_out(const float* __restrict__ x,
           const float* __restrict__ wvlw, const float* __restrict__ wvlb,
           const float* __restrict__ cenw, const float* __restrict__ cenb,
           const float* __restrict__ outw, const float* __restrict__ outb,
           float* __restrict__ y) {
    __shared__ __align__(16) __half s_in[64 * 136];   // [node][x(64)|U'(64)] padded
    __shared__ __align__(16) u32 s_w1[64 * 65];       // [o][k/2] layer1 (k=128)
    __shared__ __align__(16) u32 s_w2[64 * 33];       // [o][k/2] layer2 (k=64)
    __shared__ float s_finv[256];                     // 1/D per (node, head)
    __shared__ int   s_flag[256];                     // D>0 per (node, head)
    __shared__ float s_cb[64], s_ob[64], s_vb[16];

    int tid = threadIdx.x;
    int n0 = blockIdx.x * 64;
    u32* in32 = reinterpret_cast<u32*>(s_in);         // row stride 68 u32

    // finv/flags
    {
        int r = tid >> 2, hh = tid & 3;
        int n = n0 + r;
        float d = (n < NN) ? g_D[n * NHD + hh] : 0.f;
        s_finv[tid] = (d > 0.f) ? (1.f / d) : 0.f;
        s_flag[tid] = (d > 0.f) ? 1 : 0;
    }
    // stage x -> s_in cols 0..63
#pragma unroll
    for (int kq = 0; kq < 4; kq++) {
        int f = tid + kq * 256;                       // [0,1024): r=f>>4, c=f&15
        int r = f >> 4, c = f & 15;
        int n = n0 + r;
        float4 v = (n < NN) ? reinterpret_cast<const float4*>(x)[(size_t)n * 16 + c]
                            : make_float4(0.f, 0.f, 0.f, 0.f);
        in32[r * 68 + c * 2 + 0] = h2(v.x, v.y);
        in32[r * 68 + c * 2 + 1] = h2(v.z, v.w);
    }
    // stage layer1 weights: W1[i][o]: i<64 -> cenw[o][i]; i>=64 -> wvl blockdiag
    for (int idx = tid; idx < 64 * 64; idx += 256) {  // [o][k2]
        int o = idx >> 6, k2 = idx & 63;
        int i0 = 2 * k2, i1 = i0 + 1;
        float a, b;
        if (i0 < 64) {
            a = cenw[o * 64 + i0];
            b = cenw[o * 64 + i1];
        } else {
            int ip0 = i0 - 64, ip1 = i1 - 64;
            int oh = o >> 4;
            a = ((ip0 >> 4) == oh) ? wvlw[(o & 15) * 16 + (ip0 & 15)] : 0.f;
            b = ((ip1 >> 4) == oh) ? wvlw[(o & 15) * 16 + (ip1 & 15)] : 0.f;
        }
        s_w1[o * 65 + k2] = h2(a, b);
    }
    // stage layer2 weights
    for (int idx = tid; idx < 64 * 32; idx += 256) {
        int o = idx >> 5, k2 = idx & 31;
        s_w2[o * 33 + k2] = h2(outw[o * 64 + 2 * k2], outw[o * 64 + 2 * k2 + 1]);
    }
    if (tid < 64) { s_cb[tid] = cenb[tid]; s_ob[tid] = outb[tid]; }
    if (tid < 16) s_vb[tid] = wvlb[tid];
    __syncthreads();

    // stage U' = U * finv -> s_in cols 64..127
#pragma unroll
    for (int kq = 0; kq < 4; kq++) {
        int f = tid + kq * 256;
        int r = f >> 4, c = f & 15;                   // c = float4 idx; head = c>>2
        int n = n0 + r;
        float4 v = (n < NN) ? reinterpret_cast<const float4*>(g_U)[(size_t)n * 16 + c]
                            : make_float4(0.f, 0.f, 0.f, 0.f);
        float inv = s_finv[r * 4 + (c >> 2)];
        in32[r * 68 + 32 + c * 2 + 0] = h2(v.x * inv, v.y * inv);
        in32[r * 68 + 32 + c * 2 + 1] = h2(v.z * inv, v.w * inv);
    }
    __syncthreads();

    int lane = tid & 31;
    int g = lane >> 2, t = lane & 3;
    int warp = tid >> 5;
    int mt = warp & 3;                                // m-tile (16 nodes)
    int nh = warp >> 2;                               // n-half (0: cols 0..31, 1: 32..63)
    int r0 = mt * 16 + g, r1 = r0 + 8;

    // ---- layer1: C[nt] over this warp's 4 n-tiles, k = 128 (8 k-tiles) ----
    float C[4][4];
#pragma unroll
    for (int nt = 0; nt < 4; nt++)
        C[nt][0] = C[nt][1] = C[nt][2] = C[nt][3] = 0.f;
#pragma unroll
    for (int kk = 0; kk < 8; kk++) {
        u32 A[4];
        A[0] = in32[r0 * 68 + kk * 8 + t];
        A[1] = in32[r1 * 68 + kk * 8 + t];
        A[2] = in32[r0 * 68 + kk * 8 + 4 + t];
        A[3] = in32[r1 * 68 + kk * 8 + 4 + t];
#pragma unroll
        for (int nt = 0; nt < 4; nt++) {
            int j = (nh * 4 + nt) * 8 + g;
            u32 B[2];
            B[0] = s_w1[j * 65 + kk * 8 + t];
            B[1] = s_w1[j * 65 + kk * 8 + 4 + t];
            mma16816(C[nt], A, B);
        }
    }

    // bias + conditional vb + ssp; exchange t through s_in (overwrite, synced)
    __syncthreads();
#pragma unroll
    for (int nt = 0; nt < 4; nt++) {
        int col0 = (nh * 4 + nt) * 8 + 2 * t;
        int head = col0 >> 4;
        float vb0 = s_vb[col0 & 15], vb1 = s_vb[(col0 + 1) & 15];
        float cb0 = s_cb[col0], cb1 = s_cb[col0 + 1];
        int f0 = s_flag[r0 * 4 + head], f1 = s_flag[r1 * 4 + head];
        float t00 = ssp(C[nt][0] + cb0 + (f0 ? vb0 : 0.f));
        float t01 = ssp(C[nt][1] + cb1 + (f0 ? vb1 : 0.f));
        float t10 = ssp(C[nt][2] + cb0 + (f1 ? vb0 : 0.f));
        float t11 = ssp(C[nt][3] + cb1 + (f1 ? vb1 : 0.f));
        in32[r0 * 68 + col0 / 2] = h2(t00, t01);
        in32[r1 * 68 + col0 / 2] = h2(t10, t11);
    }
    __syncthreads();

    // ---- layer2: y = outw @ t + ob, k = 64 (4 k-tiles) ----
    float D[4][4];
#pragma unroll
    for (int nt = 0; nt < 4; nt++)
        D[nt][0] = D[nt][1] = D[nt][2] = D[nt][3] = 0.f;
#pragma unroll
    for (int kk = 0; kk < 4; kk++) {
        u32 A[4];
        A[0] = in32[r0 * 68 + kk * 8 + t];
        A[1] = in32[r1 * 68 + kk * 8 + t];
        A[2] = in32[r0 * 68 + kk * 8 + 4 + t];
        A[3] = in32[r1 * 68 + kk * 8 + 4 + t];
#pragma unroll
        for (int nt = 0; nt < 4; nt++) {
            int j = (nh * 4 + nt) * 8 + g;
            u32 B[2];
            B[0] = s_w2[j * 33 + kk * 8 + t];
            B[1] = s_w2[j * 33 + kk * 8 + 4 + t];
            mma16816(D[nt], A, B);
        }
    }

    int nn0 = n0 + r0, nn1 = n0 + r1;
#pragma unroll
    for (int nt = 0; nt < 4; nt++) {
        int col = (nh * 4 + nt) * 8 + 2 * t;
        float ob0 = s_ob[col], ob1 = s_ob[col + 1];
        if (nn0 < NN)
            *reinterpret_cast<float2*>(y + (size_t)nn0 * HCH + col) =
                make_float2(D[nt][0] + ob0, D[nt][1] + ob1);
        if (nn1 < NN)
            *reinterpret_cast<float2*>(y + (size_t)nn1 * HCH + col) =
                make_float2(D[nt][2] + ob0, D[nt][3] + ob1);
    }
}

// ---------------------------------------------------------------------------
extern "C" void kernel_launch(void* const* d_in, const int* in_sizes, int n_in,
                              void* d_out, int out_size) {
    const float* x    = (const float*)d_in[0];
    const int*   ei   = (const int*)d_in[1];
    const float* ea   = (const float*)d_in[2];
    const float* kw   = (const float*)d_in[3];
    const float* qw   = (const float*)d_in[4];
    const float* vw   = (const float*)d_in[5];
    const float* wk1  = (const float*)d_in[6];
    const float* bk1  = (const float*)d_in[7];
    const float* wk2  = (const float*)d_in[8];
    const float* bk2  = (const float*)d_in[9];
    const float* wklw = (const float*)d_in[10];
    const float* wklb = (const float*)d_in[11];
    const float* wv1  = (const float*)d_in[12];
    const float* bv1  = (const float*)d_in[13];
    const float* wv2  = (const float*)d_in[14];
    const float* bv2  = (const float*)d_in[15];
    const float* wvlw = (const float*)d_in[16];
    const float* wvlb = (const float*)d_in[17];
    const float* cenw = (const float*)d_in[18];
    const float* cenb = (const float*)d_in[19];
    const float* outw = (const float*)d_in[20];
    const float* outb = (const float*)d_in[21];
    float* out = (float*)d_out;

    k_detect<<<1, 256>>>(ei);
    k_nodes<<<(NN * NHD + 255) / 256, 256>>>(x, kw, qw, vw, wklw, wklb);
    k_mlp<<<MLP_GRID, 256>>>(ea, wk1, bk1, wk2, bk2, wv1, bv1, wv2, bv2);
    k_attn<<<(EE * NHD) / 256, 256>>>(ei);
    k_out<<<(NN + 63) / 64, 256>>>(x, wvlw, wvlb, cenw, cenb,
                                   outw, outb, out);
}